// round 9
// baseline (speedup 1.0000x reference)
#include <cuda_runtime.h>
#include <cuda_bf16.h>
#include <math.h>
#include <stdint.h>

// Problem constants
#define BB   8
#define TT   1024
#define CC   1024
#define HHD  16
#define DD   64
#define NROWS (BB*TT)      // 8192
#define FFN   (4*CC)       // 4096
#define QKVN 3072
#define EPS  1e-5f

// -------------------- scratch (static device memory; no allocs) ------------
// bf16 hi/lo activations
__device__ __nv_bfloat16 g_hh [(size_t)NROWS*CC];
__device__ __nv_bfloat16 g_hl [(size_t)NROWS*CC];
__device__ __nv_bfloat16 g_ctxh[(size_t)NROWS*CC];
__device__ __nv_bfloat16 g_ctxl[(size_t)NROWS*CC];
__device__ __nv_bfloat16 g_ffh[(size_t)NROWS*FFN];
__device__ __nv_bfloat16 g_ffl[(size_t)NROWS*FFN];
// fp32 buffers
__device__ float g_qkv[(size_t)NROWS*QKVN];
__device__ float g_x2 [(size_t)NROWS*CC];
// bf16 hi/lo transposed weights [N][K] K-major
__device__ __nv_bfloat16 g_wqkvTh[(size_t)QKVN*CC];
__device__ __nv_bfloat16 g_wqkvTl[(size_t)QKVN*CC];
__device__ __nv_bfloat16 g_woTh[(size_t)CC*CC];
__device__ __nv_bfloat16 g_woTl[(size_t)CC*CC];
__device__ __nv_bfloat16 g_w1Th[(size_t)FFN*CC];
__device__ __nv_bfloat16 g_w1Tl[(size_t)FFN*CC];
__device__ __nv_bfloat16 g_w2Th[(size_t)CC*FFN];
__device__ __nv_bfloat16 g_w2Tl[(size_t)CC*FFN];
__device__ float g_bqkv[QKVN];

// ---------------------------- helpers ---------------------------------------
__device__ __forceinline__ uint32_t smem_to_u32(const void* p) {
    uint32_t a;
    asm("{ .reg .u64 t; cvta.to.shared.u64 t, %1; cvt.u32.u64 %0, t; }"
        : "=r"(a) : "l"(p));
    return a;
}
__device__ __forceinline__ void ldsm_x4(uint32_t* r, uint32_t addr) {
    asm volatile("ldmatrix.sync.aligned.m8n8.x4.shared.b16 {%0,%1,%2,%3}, [%4];"
                 : "=r"(r[0]), "=r"(r[1]), "=r"(r[2]), "=r"(r[3]) : "r"(addr));
}
__device__ __forceinline__ void mma_bf16(float* c, const uint32_t* a,
                                         const uint32_t* b) {
    asm volatile(
        "mma.sync.aligned.m16n8k16.row.col.f32.bf16.bf16.f32 "
        "{%0,%1,%2,%3}, {%4,%5,%6,%7}, {%8,%9}, {%0,%1,%2,%3};"
        : "+f"(c[0]), "+f"(c[1]), "+f"(c[2]), "+f"(c[3])
        : "r"(a[0]), "r"(a[1]), "r"(a[2]), "r"(a[3]), "r"(b[0]), "r"(b[1]));
}
#define CP16(sa, gp) \
    asm volatile("cp.async.cg.shared.global [%0], [%1], 16;" \
                 :: "r"(sa), "l"(gp) : "memory")
#define CP_COMMIT() asm volatile("cp.async.commit_group;" ::: "memory")
#define CP_WAIT2()  asm volatile("cp.async.wait_group 2;" ::: "memory")

__device__ __forceinline__ float gelu_exact(float v) {
    return 0.5f * v * (1.0f + erff(v * 0.70710678118654752f));
}
// split a float pair into bf16 hi/lo pairs and store
__device__ __forceinline__ void split_store2(__nv_bfloat16* Ch, __nv_bfloat16* Cl,
                                             size_t off, float x, float y) {
    __nv_bfloat162 h, l;
    h.x = __float2bfloat16_rn(x); h.y = __float2bfloat16_rn(y);
    l.x = __float2bfloat16_rn(x - __bfloat162float(h.x));
    l.y = __float2bfloat16_rn(y - __bfloat162float(h.y));
    *(__nv_bfloat162*)(Ch + off) = h;
    *(__nv_bfloat162*)(Cl + off) = l;
}

// --------------------------- weight transpose + split ------------------------
// WTh/WTl[n][k] = split(W[k][n]).
__global__ __launch_bounds__(256) void transpose_split_kernel(
    const float* __restrict__ W, __nv_bfloat16* __restrict__ WTh,
    __nv_bfloat16* __restrict__ WTl, int K, int N)
{
    __shared__ float t[32][33];
    const int n0 = blockIdx.x * 32, k0 = blockIdx.y * 32;
    const int tx = threadIdx.x, ty = threadIdx.y;
    #pragma unroll
    for (int i = 0; i < 32; i += 8)
        t[ty + i][tx] = W[(size_t)(k0 + ty + i) * N + n0 + tx];
    __syncthreads();
    #pragma unroll
    for (int i = 0; i < 32; i += 8) {
        float v = t[tx][ty + i];
        __nv_bfloat16 h = __float2bfloat16_rn(v);
        __nv_bfloat16 l = __float2bfloat16_rn(v - __bfloat162float(h));
        const size_t off = (size_t)(n0 + ty + i) * K + k0 + tx;
        WTh[off] = h;
        WTl[off] = l;
    }
}

__global__ void bias_concat_kernel(const float* bq, const float* bk,
                                   const float* bv, float* out)
{
    int i = blockIdx.x * blockDim.x + threadIdx.x;
    if (i < 1024)       out[i] = bq[i];
    else if (i < 2048)  out[i] = bk[i - 1024];
    else if (i < 3072)  out[i] = bv[i - 2048];
}

// ---------------------------- LayerNorm (split bf16 out) --------------------
__global__ __launch_bounds__(256) void ln_split_kernel(
    const float* __restrict__ x, const float* __restrict__ w,
    const float* __restrict__ b, __nv_bfloat16* __restrict__ outh,
    __nv_bfloat16* __restrict__ outl)
{
    const int row = blockIdx.x;
    const int tid = threadIdx.x;
    const float4* xr = (const float4*)(x + (size_t)row * CC);
    float4 v = xr[tid];
    float s  = v.x + v.y + v.z + v.w;
    float ss = v.x*v.x + v.y*v.y + v.z*v.z + v.w*v.w;

    __shared__ float red0[8], red1[8];
    #pragma unroll
    for (int o = 16; o > 0; o >>= 1) {
        s  += __shfl_down_sync(0xffffffffu, s,  o);
        ss += __shfl_down_sync(0xffffffffu, ss, o);
    }
    const int wid = tid >> 5, lid = tid & 31;
    if (lid == 0) { red0[wid] = s; red1[wid] = ss; }
    __syncthreads();
    if (tid == 0) {
        float S = 0.f, SS = 0.f;
        #pragma unroll
        for (int i = 0; i < 8; i++) { S += red0[i]; SS += red1[i]; }
        float mu  = S * (1.f / CC);
        float var = SS * (1.f / CC) - mu * mu;
        red0[0] = mu;
        red1[0] = rsqrtf(var + EPS);
    }
    __syncthreads();
    const float mu = red0[0], rstd = red1[0];
    float4 wv = ((const float4*)w)[tid];
    float4 bv = ((const float4*)b)[tid];
    float ox = (v.x - mu) * rstd * wv.x + bv.x;
    float oy = (v.y - mu) * rstd * wv.y + bv.y;
    float oz = (v.z - mu) * rstd * wv.z + bv.z;
    float ow = (v.w - mu) * rstd * wv.w + bv.w;
    const size_t off = (size_t)row * CC + tid * 4;
    split_store2(outh, outl, off,     ox, oy);
    split_store2(outh, outl, off + 2, oz, ow);
}

// --------------------- bf16x3 cp.async pipelined GEMM -----------------------
// C[M,N] = epilogue(A[M,K] @ BT[N,K]^T + bias, res)
// Operands pre-split: Ah/Al, Bh/Bl bf16 K-major.
// EPI 0: C=+bias(fp32)  EPI 1: C=+bias+res(fp32)  EPI 2: Ch/Cl=split(gelu(+bias))
// CTA 128x128x32, 256 thr, warps 4(m) x 2(n); 4-stage cp.async pipeline.

#define PITCH      80
#define TILE_B     (128 * PITCH)               // 10240
#define SOFF(st,w) (((st)*4 + (w)) * TILE_B)
#define GEMM_SMEM  (16 * TILE_B)               // 163840 (4 stages x 4 tiles)

__device__ __forceinline__ void stage_load(
    uint32_t sb, int st,
    const __nv_bfloat16* Ah, const __nv_bfloat16* Al,
    const __nv_bfloat16* Bh, const __nv_bfloat16* Bl,
    int kb, int tid, int K)
{
    const int r  = tid >> 1;               // 0..127
    const int c0 = (tid & 1) * 2;          // chunk 0/2 (16B chunks of 8 bf16)
    const size_t gbase = (size_t)r * K + (size_t)kb * 32 + c0 * 8;
    const uint32_t sbase = sb + (uint32_t)(r * PITCH + c0 * 16);
    const __nv_bfloat16* ptrs[4] = {Ah, Al, Bh, Bl};
    #pragma unroll
    for (int w = 0; w < 4; w++) {
        const __nv_bfloat16* g = ptrs[w] + gbase;
        const uint32_t s = sbase + SOFF(st, w);
        CP16(s,      g);
        CP16(s + 16, g + 8);
    }
}

template<int EPI>
__global__ __launch_bounds__(256, 1) void gemm_bf16_pipe(
    const __nv_bfloat16* __restrict__ Ah, const __nv_bfloat16* __restrict__ Al,
    const __nv_bfloat16* __restrict__ Bh, const __nv_bfloat16* __restrict__ Bl,
    const float* __restrict__ bias, const float* __restrict__ res,
    float* __restrict__ C, __nv_bfloat16* __restrict__ Ch,
    __nv_bfloat16* __restrict__ Cl, int M, int N, int K)
{
    extern __shared__ char smemc[];
    const uint32_t sb = smem_to_u32(smemc);

    const int tid    = threadIdx.x;
    const int wid    = tid >> 5, lane = tid & 31;
    const int warp_m = wid & 3;
    const int warp_n = wid >> 2;
    const int brow   = blockIdx.y * 128;
    const int bcol   = blockIdx.x * 128;

    const __nv_bfloat16* Agh = Ah + (size_t)brow * K;
    const __nv_bfloat16* Agl = Al + (size_t)brow * K;
    const __nv_bfloat16* Bgh = Bh + (size_t)bcol * K;
    const __nv_bfloat16* Bgl = Bl + (size_t)bcol * K;

    float acc[64];
    #pragma unroll
    for (int i = 0; i < 64; i++) acc[i] = 0.f;

    const int NKB = K >> 5;

    // prologue: fill 3 stages
    #pragma unroll
    for (int s = 0; s < 3; s++) {
        stage_load(sb, s, Agh, Agl, Bgh, Bgl, s, tid, K);
        CP_COMMIT();
    }

    // ldmatrix per-lane offsets (within a tile)
    const int a_row = warp_m * 32 + (lane & 7) + ((lane >> 3) & 1) * 8;
    const uint32_t a_off = (uint32_t)(a_row * PITCH + (lane >> 4) * 16);
    const int b_row = warp_n * 64 + (lane & 7) + (lane >> 4) * 8;
    const uint32_t b_off = (uint32_t)(b_row * PITCH + ((lane >> 3) & 1) * 16);

    for (int kb = 0; kb < NKB; kb++) {
        CP_WAIT2();
        __syncthreads();

        const int kn = kb + 3;
        if (kn < NKB)
            stage_load(sb, kn & 3, Agh, Agl, Bgh, Bgl, kn, tid, K);
        CP_COMMIT();

        const int st = kb & 3;
        const uint32_t sAh = sb + SOFF(st,0), sAl = sb + SOFF(st,1);
        const uint32_t sBh = sb + SOFF(st,2), sBl = sb + SOFF(st,3);

        #pragma unroll
        for (int k16 = 0; k16 < 2; k16++) {
            uint32_t ah[2][4], al[2][4];
            #pragma unroll
            for (int mt = 0; mt < 2; mt++) {
                const uint32_t off = a_off + mt * 16 * PITCH + k16 * 32;
                ldsm_x4(ah[mt], sAh + off);
                ldsm_x4(al[mt], sAl + off);
            }
            #pragma unroll
            for (int nt = 0; nt < 4; nt++) {
                uint32_t bh[4], bl[4];
                const uint32_t off = b_off + nt * 16 * PITCH + k16 * 32;
                ldsm_x4(bh, sBh + off);
                ldsm_x4(bl, sBl + off);
                #pragma unroll
                for (int mt = 0; mt < 2; mt++)
                    #pragma unroll
                    for (int t = 0; t < 2; t++)
                        mma_bf16(&acc[(mt*8 + nt*2 + t)*4], ah[mt], &bl[t*2]);
                #pragma unroll
                for (int mt = 0; mt < 2; mt++)
                    #pragma unroll
                    for (int t = 0; t < 2; t++)
                        mma_bf16(&acc[(mt*8 + nt*2 + t)*4], al[mt], &bh[t*2]);
                #pragma unroll
                for (int mt = 0; mt < 2; mt++)
                    #pragma unroll
                    for (int t = 0; t < 2; t++)
                        mma_bf16(&acc[(mt*8 + nt*2 + t)*4], ah[mt], &bh[t*2]);
            }
        }
        __syncthreads();
    }

    // ---------------- epilogue ----------------
    const int erow = brow + warp_m * 32 + (lane >> 2);
    const int ecol = bcol + warp_n * 64 + (lane & 3) * 2;
    #pragma unroll
    for (int mt = 0; mt < 2; mt++) {
        #pragma unroll
        for (int j = 0; j < 8; j++) {
            const float* c = &acc[(mt*8 + j)*4];
            const int grow = erow + mt * 16;
            const int gcol = ecol + j * 8;
            float2 bvv = *(const float2*)(bias + gcol);
            float o0x = c[0] + bvv.x, o0y = c[1] + bvv.y;
            float o1x = c[2] + bvv.x, o1y = c[3] + bvv.y;
            if (EPI == 1) {
                float2 r0v = *(const float2*)(res + (size_t)grow * N + gcol);
                float2 r1v = *(const float2*)(res + (size_t)(grow+8) * N + gcol);
                o0x += r0v.x; o0y += r0v.y;
                o1x += r1v.x; o1y += r1v.y;
            }
            if (EPI == 2) {
                o0x = gelu_exact(o0x); o0y = gelu_exact(o0y);
                o1x = gelu_exact(o1x); o1y = gelu_exact(o1y);
                split_store2(Ch, Cl, (size_t)grow * N + gcol,     o0x, o0y);
                split_store2(Ch, Cl, (size_t)(grow+8) * N + gcol, o1x, o1y);
            } else {
                float2 o0 = make_float2(o0x, o0y);
                float2 o1 = make_float2(o1x, o1y);
                *(float2*)(C + (size_t)grow * N + gcol)     = o0;
                *(float2*)(C + (size_t)(grow+8) * N + gcol) = o1;
            }
        }
    }
}

// --------------------------- Flash attention --------------------------------
// Reads q/k/v from fused qkv buffer (row stride QKVN), writes ctx hi/lo bf16.
__global__ __launch_bounds__(64) void flash_kernel(
    const float* __restrict__ QKV, __nv_bfloat16* __restrict__ Oh,
    __nv_bfloat16* __restrict__ Ol)
{
    __shared__ float Ks[32][64];
    __shared__ float Vs[32][64];
    __shared__ float Ss[32][64];

    const int qt  = blockIdx.x;
    const int bh  = blockIdx.y;
    const int b   = bh >> 4;
    const int hh  = bh & 15;
    const int tid = threadIdx.x;
    const int qrow = qt * 64 + tid;

    const size_t qbase = ((size_t)b * TT) * QKVN + (size_t)hh * DD;
    const float* Qp = QKV + qbase;
    const float* Kp = QKV + qbase + 1024;
    const float* Vp = QKV + qbase + 2048;

    float4 q4[16], o4[16];
    {
        const float4* qp = (const float4*)(Qp + (size_t)qrow * QKVN);
        #pragma unroll
        for (int i = 0; i < 16; i++) {
            q4[i] = qp[i];
            o4[i] = make_float4(0.f, 0.f, 0.f, 0.f);
        }
    }
    float m = -INFINITY, l = 0.f;

    const int nkt = 2 * qt + 2;
    for (int kt = 0; kt < nkt; kt++) {
        const float* kbase = Kp + (size_t)(kt * 32) * QKVN;
        const float* vbase = Vp + (size_t)(kt * 32) * QKVN;
        #pragma unroll
        for (int i = 0; i < 8; i++) {
            int p = i * 64 + tid;
            int r = p >> 4, c = p & 15;
            ((float4*)&Ks[r][0])[c] = ((const float4*)(kbase + (size_t)r * QKVN))[c];
            ((float4*)&Vs[r][0])[c] = ((const float4*)(vbase + (size_t)r * QKVN))[c];
        }
        __syncthreads();

        int jhi = qrow - kt * 32 + 1;
        if (jhi > 32) jhi = 32;
        if (jhi > 0) {
            float tmax = -INFINITY;
            #pragma unroll 2
            for (int j = 0; j < jhi; j++) {
                float4 a = make_float4(0.f, 0.f, 0.f, 0.f);
                #pragma unroll
                for (int i = 0; i < 16; i++) {
                    float4 kv = ((const float4*)&Ks[j][0])[i];
                    a.x = fmaf(q4[i].x, kv.x, a.x);
                    a.y = fmaf(q4[i].y, kv.y, a.y);
                    a.z = fmaf(q4[i].z, kv.z, a.z);
                    a.w = fmaf(q4[i].w, kv.w, a.w);
                }
                float sj = ((a.x + a.y) + (a.z + a.w)) * 0.125f;
                Ss[j][tid] = sj;
                tmax = fmaxf(tmax, sj);
            }
            float mnew  = fmaxf(m, tmax);
            float alpha = __expf(m - mnew);
            l *= alpha;
            #pragma unroll
            for (int i = 0; i < 16; i++) {
                o4[i].x *= alpha; o4[i].y *= alpha;
                o4[i].z *= alpha; o4[i].w *= alpha;
            }
            #pragma unroll 2
            for (int j = 0; j < jhi; j++) {
                float p = __expf(Ss[j][tid] - mnew);
                l += p;
                #pragma unroll
                for (int i = 0; i < 16; i++) {
                    float4 vv = ((const float4*)&Vs[j][0])[i];
                    o4[i].x = fmaf(p, vv.x, o4[i].x);
                    o4[i].y = fmaf(p, vv.y, o4[i].y);
                    o4[i].z = fmaf(p, vv.z, o4[i].z);
                    o4[i].w = fmaf(p, vv.w, o4[i].w);
                }
            }
            m = mnew;
        }
        __syncthreads();
    }

    const float inv = 1.f / l;
    const size_t obase = ((size_t)b * TT) * CC + (size_t)hh * DD
                       + (size_t)qrow * CC;
    #pragma unroll
    for (int i = 0; i < 16; i++) {
        split_store2(Oh, Ol, obase + i*4,     o4[i].x * inv, o4[i].y * inv);
        split_store2(Oh, Ol, obase + i*4 + 2, o4[i].z * inv, o4[i].w * inv);
    }
}

// ------------------------------ launch --------------------------------------
extern "C" void kernel_launch(void* const* d_in, const int* in_sizes, int n_in,
                              void* d_out, int out_size)
{
    (void)in_sizes; (void)n_in; (void)out_size;
    const float* x    = (const float*)d_in[0];
    const float* ln1w = (const float*)d_in[2];
    const float* ln1b = (const float*)d_in[3];
    const float* ln2w = (const float*)d_in[4];
    const float* ln2b = (const float*)d_in[5];
    const float* wq   = (const float*)d_in[6];
    const float* bq   = (const float*)d_in[7];
    const float* wk   = (const float*)d_in[8];
    const float* bk   = (const float*)d_in[9];
    const float* wv   = (const float*)d_in[10];
    const float* bv   = (const float*)d_in[11];
    const float* wo   = (const float*)d_in[12];
    const float* bo   = (const float*)d_in[13];
    const float* w1   = (const float*)d_in[14];
    const float* b1   = (const float*)d_in[15];
    const float* w2   = (const float*)d_in[16];
    const float* b2   = (const float*)d_in[17];
    float* out = (float*)d_out;

    __nv_bfloat16 *hh, *hl, *ctxh, *ctxl, *ffh, *ffl;
    __nv_bfloat16 *wqkvTh, *wqkvTl, *woTh, *woTl, *w1Th, *w1Tl, *w2Th, *w2Tl;
    float *qkv, *x2, *bqkv;
    cudaGetSymbolAddress((void**)&hh,   g_hh);
    cudaGetSymbolAddress((void**)&hl,   g_hl);
    cudaGetSymbolAddress((void**)&ctxh, g_ctxh);
    cudaGetSymbolAddress((void**)&ctxl, g_ctxl);
    cudaGetSymbolAddress((void**)&ffh,  g_ffh);
    cudaGetSymbolAddress((void**)&ffl,  g_ffl);
    cudaGetSymbolAddress((void**)&qkv,  g_qkv);
    cudaGetSymbolAddress((void**)&x2,   g_x2);
    cudaGetSymbolAddress((void**)&bqkv, g_bqkv);
    cudaGetSymbolAddress((void**)&wqkvTh, g_wqkvTh);
    cudaGetSymbolAddress((void**)&wqkvTl, g_wqkvTl);
    cudaGetSymbolAddress((void**)&woTh, g_woTh);
    cudaGetSymbolAddress((void**)&woTl, g_woTl);
    cudaGetSymbolAddress((void**)&w1Th, g_w1Th);
    cudaGetSymbolAddress((void**)&w1Tl, g_w1Tl);
    cudaGetSymbolAddress((void**)&w2Th, g_w2Th);
    cudaGetSymbolAddress((void**)&w2Tl, g_w2Tl);

    cudaFuncSetAttribute(gemm_bf16_pipe<0>, cudaFuncAttributeMaxDynamicSharedMemorySize, GEMM_SMEM);
    cudaFuncSetAttribute(gemm_bf16_pipe<1>, cudaFuncAttributeMaxDynamicSharedMemorySize, GEMM_SMEM);
    cudaFuncSetAttribute(gemm_bf16_pipe<2>, cudaFuncAttributeMaxDynamicSharedMemorySize, GEMM_SMEM);

    const dim3 tB(32, 8);
    // fused QKV weight: rows 0..1023 = wq^T, 1024..2047 = wk^T, 2048..3071 = wv^T
    transpose_split_kernel<<<dim3(CC/32,  CC/32),  tB>>>(wq, wqkvTh,              wqkvTl,              CC,  CC);
    transpose_split_kernel<<<dim3(CC/32,  CC/32),  tB>>>(wk, wqkvTh + 1024*CC,    wqkvTl + 1024*CC,    CC,  CC);
    transpose_split_kernel<<<dim3(CC/32,  CC/32),  tB>>>(wv, wqkvTh + 2048*CC,    wqkvTl + 2048*CC,    CC,  CC);
    transpose_split_kernel<<<dim3(CC/32,  CC/32),  tB>>>(wo, woTh, woTl, CC,  CC);
    transpose_split_kernel<<<dim3(FFN/32, CC/32),  tB>>>(w1, w1Th, w1Tl, CC,  FFN);
    transpose_split_kernel<<<dim3(CC/32,  FFN/32), tB>>>(w2, w2Th, w2Tl, FFN, CC);
    bias_concat_kernel<<<12, 256>>>(bq, bk, bv, bqkv);

    const dim3 gQKV(QKVN / 128, NROWS / 128);   // 24 x 64
    const dim3 gC  (CC   / 128, NROWS / 128);   // 8 x 64
    const dim3 gF  (FFN  / 128, NROWS / 128);   // 32 x 64

    // 1. h = LN1(x)  (bf16 hi/lo)
    ln_split_kernel<<<NROWS, 256>>>(x, ln1w, ln1b, hh, hl);
    // 2. qkv = h@Wqkv + bqkv  (fused, fp32 out)
    gemm_bf16_pipe<0><<<gQKV, 256, GEMM_SMEM>>>(hh, hl, wqkvTh, wqkvTl, bqkv,
                                                nullptr, qkv, nullptr, nullptr,
                                                NROWS, QKVN, CC);
    // 3. ctx = causal-softmax(qk^T/8) v  (bf16 hi/lo out)
    flash_kernel<<<dim3(TT / 64, BB * HHD), 64>>>(qkv, ctxh, ctxl);
    // 4. x2 = x + ctx@wo + bo
    gemm_bf16_pipe<1><<<gC, 256, GEMM_SMEM>>>(ctxh, ctxl, woTh, woTl, bo, x,
                                              x2, nullptr, nullptr,
                                              NROWS, CC, CC);
    // 5. h = LN2(x2)  (bf16 hi/lo)
    ln_split_kernel<<<NROWS, 256>>>(x2, ln2w, ln2b, hh, hl);
    // 6. ff = gelu(h@w1 + b1)  (bf16 hi/lo out)
    gemm_bf16_pipe<2><<<gF, 256, GEMM_SMEM>>>(hh, hl, w1Th, w1Tl, b1, nullptr,
                                              nullptr, ffh, ffl,
                                              NROWS, FFN, CC);
    // 7. out = x2 + ff@w2 + b2
    gemm_bf16_pipe<1><<<gC, 256, GEMM_SMEM>>>(ffh, ffl, w2Th, w2Tl, b2, x2,
                                              out, nullptr, nullptr,
                                              NROWS, CC, FFN);
}

// round 10
// speedup vs baseline: 1.1137x; 1.1137x over previous
#include <cuda_runtime.h>
#include <cuda_bf16.h>
#include <math.h>
#include <stdint.h>

// Problem constants
#define BB   8
#define TT   1024
#define CC   1024
#define HHD  16
#define DD   64
#define NROWS (BB*TT)      // 8192
#define FFN   (4*CC)       // 4096
#define QKVN 3072
#define EPS  1e-5f

// -------------------- scratch (static device memory; no allocs) ------------
// bf16 hi/lo activations
__device__ __nv_bfloat16 g_hh [(size_t)NROWS*CC];
__device__ __nv_bfloat16 g_hl [(size_t)NROWS*CC];
__device__ __nv_bfloat16 g_ctxh[(size_t)NROWS*CC];
__device__ __nv_bfloat16 g_ctxl[(size_t)NROWS*CC];
__device__ __nv_bfloat16 g_ffh[(size_t)NROWS*FFN];
__device__ __nv_bfloat16 g_ffl[(size_t)NROWS*FFN];
// fp32 buffers
__device__ float g_qkv[(size_t)NROWS*QKVN];
__device__ float g_x2 [(size_t)NROWS*CC];
// bf16 hi/lo transposed weights [N][K] K-major
__device__ __nv_bfloat16 g_wqkvTh[(size_t)QKVN*CC];
__device__ __nv_bfloat16 g_wqkvTl[(size_t)QKVN*CC];
__device__ __nv_bfloat16 g_woTh[(size_t)CC*CC];
__device__ __nv_bfloat16 g_woTl[(size_t)CC*CC];
__device__ __nv_bfloat16 g_w1Th[(size_t)FFN*CC];
__device__ __nv_bfloat16 g_w1Tl[(size_t)FFN*CC];
__device__ __nv_bfloat16 g_w2Th[(size_t)CC*FFN];
__device__ __nv_bfloat16 g_w2Tl[(size_t)CC*FFN];
__device__ float g_bqkv[QKVN];

// ---------------------------- helpers ---------------------------------------
__device__ __forceinline__ uint32_t smem_to_u32(const void* p) {
    uint32_t a;
    asm("{ .reg .u64 t; cvta.to.shared.u64 t, %1; cvt.u32.u64 %0, t; }"
        : "=r"(a) : "l"(p));
    return a;
}
__device__ __forceinline__ void ldsm_x4(uint32_t* r, uint32_t addr) {
    asm volatile("ldmatrix.sync.aligned.m8n8.x4.shared.b16 {%0,%1,%2,%3}, [%4];"
                 : "=r"(r[0]), "=r"(r[1]), "=r"(r[2]), "=r"(r[3]) : "r"(addr));
}
__device__ __forceinline__ void mma_bf16(float* c, const uint32_t* a,
                                         const uint32_t* b) {
    asm volatile(
        "mma.sync.aligned.m16n8k16.row.col.f32.bf16.bf16.f32 "
        "{%0,%1,%2,%3}, {%4,%5,%6,%7}, {%8,%9}, {%0,%1,%2,%3};"
        : "+f"(c[0]), "+f"(c[1]), "+f"(c[2]), "+f"(c[3])
        : "r"(a[0]), "r"(a[1]), "r"(a[2]), "r"(a[3]), "r"(b[0]), "r"(b[1]));
}
#define CP16(sa, gp) \
    asm volatile("cp.async.cg.shared.global [%0], [%1], 16;" \
                 :: "r"(sa), "l"(gp) : "memory")
#define CP_COMMIT() asm volatile("cp.async.commit_group;" ::: "memory")
#define CP_WAIT1()  asm volatile("cp.async.wait_group 1;" ::: "memory")

__device__ __forceinline__ float gelu_exact(float v) {
    return 0.5f * v * (1.0f + erff(v * 0.70710678118654752f));
}
// split a float pair into bf16 hi/lo pairs and store
__device__ __forceinline__ void split_store2(__nv_bfloat16* Ch, __nv_bfloat16* Cl,
                                             size_t off, float x, float y) {
    __nv_bfloat162 h, l;
    h.x = __float2bfloat16_rn(x); h.y = __float2bfloat16_rn(y);
    l.x = __float2bfloat16_rn(x - __bfloat162float(h.x));
    l.y = __float2bfloat16_rn(y - __bfloat162float(h.y));
    *(__nv_bfloat162*)(Ch + off) = h;
    *(__nv_bfloat162*)(Cl + off) = l;
}

// --------------------------- weight transpose + split ------------------------
__global__ __launch_bounds__(256) void transpose_split_kernel(
    const float* __restrict__ W, __nv_bfloat16* __restrict__ WTh,
    __nv_bfloat16* __restrict__ WTl, int K, int N)
{
    __shared__ float t[32][33];
    const int n0 = blockIdx.x * 32, k0 = blockIdx.y * 32;
    const int tx = threadIdx.x, ty = threadIdx.y;
    #pragma unroll
    for (int i = 0; i < 32; i += 8)
        t[ty + i][tx] = W[(size_t)(k0 + ty + i) * N + n0 + tx];
    __syncthreads();
    #pragma unroll
    for (int i = 0; i < 32; i += 8) {
        float v = t[tx][ty + i];
        __nv_bfloat16 h = __float2bfloat16_rn(v);
        __nv_bfloat16 l = __float2bfloat16_rn(v - __bfloat162float(h));
        const size_t off = (size_t)(n0 + ty + i) * K + k0 + tx;
        WTh[off] = h;
        WTl[off] = l;
    }
}

__global__ void bias_concat_kernel(const float* bq, const float* bk,
                                   const float* bv, float* out)
{
    int i = blockIdx.x * blockDim.x + threadIdx.x;
    if (i < 1024)       out[i] = bq[i];
    else if (i < 2048)  out[i] = bk[i - 1024];
    else if (i < 3072)  out[i] = bv[i - 2048];
}

// ---------------------------- LayerNorm (split bf16 out) --------------------
__global__ __launch_bounds__(256) void ln_split_kernel(
    const float* __restrict__ x, const float* __restrict__ w,
    const float* __restrict__ b, __nv_bfloat16* __restrict__ outh,
    __nv_bfloat16* __restrict__ outl)
{
    const int row = blockIdx.x;
    const int tid = threadIdx.x;
    const float4* xr = (const float4*)(x + (size_t)row * CC);
    float4 v = xr[tid];
    float s  = v.x + v.y + v.z + v.w;
    float ss = v.x*v.x + v.y*v.y + v.z*v.z + v.w*v.w;

    __shared__ float red0[8], red1[8];
    #pragma unroll
    for (int o = 16; o > 0; o >>= 1) {
        s  += __shfl_down_sync(0xffffffffu, s,  o);
        ss += __shfl_down_sync(0xffffffffu, ss, o);
    }
    const int wid = tid >> 5, lid = tid & 31;
    if (lid == 0) { red0[wid] = s; red1[wid] = ss; }
    __syncthreads();
    if (tid == 0) {
        float S = 0.f, SS = 0.f;
        #pragma unroll
        for (int i = 0; i < 8; i++) { S += red0[i]; SS += red1[i]; }
        float mu  = S * (1.f / CC);
        float var = SS * (1.f / CC) - mu * mu;
        red0[0] = mu;
        red1[0] = rsqrtf(var + EPS);
    }
    __syncthreads();
    const float mu = red0[0], rstd = red1[0];
    float4 wv = ((const float4*)w)[tid];
    float4 bv = ((const float4*)b)[tid];
    float ox = (v.x - mu) * rstd * wv.x + bv.x;
    float oy = (v.y - mu) * rstd * wv.y + bv.y;
    float oz = (v.z - mu) * rstd * wv.z + bv.z;
    float ow = (v.w - mu) * rstd * wv.w + bv.w;
    const size_t off = (size_t)row * CC + tid * 4;
    split_store2(outh, outl, off,     ox, oy);
    split_store2(outh, outl, off + 2, oz, ow);
}

// --------------------- bf16x3 cp.async pipelined GEMM -----------------------
// C[M,N] = epilogue(A[M,K] @ BT[N,K]^T + bias, res)
// Operands pre-split: Ah/Al, Bh/Bl bf16 K-major.
// EPI 0: C=+bias(fp32)  EPI 1: C=+bias+res(fp32)  EPI 2: Ch/Cl=split(gelu(+bias))
// CTA 128x128x32, 256 thr, warps 4(m) x 2(n); 2-stage cp.async, 2 CTAs/SM.

#define PITCH      80
#define TILE_B     (128 * PITCH)               // 10240
#define SOFF(st,w) (((st)*4 + (w)) * TILE_B)
#define GEMM_SMEM  (8 * TILE_B)                // 81920 (2 stages x 4 tiles)

__device__ __forceinline__ void stage_load(
    uint32_t sb, int st,
    const __nv_bfloat16* Ah, const __nv_bfloat16* Al,
    const __nv_bfloat16* Bh, const __nv_bfloat16* Bl,
    int kb, int tid, int K)
{
    const int r  = tid >> 1;               // 0..127
    const int c0 = (tid & 1) * 2;          // 16B chunk 0/2
    const size_t gbase = (size_t)r * K + (size_t)kb * 32 + c0 * 8;
    const uint32_t sbase = sb + (uint32_t)(r * PITCH + c0 * 16);
    const __nv_bfloat16* ptrs[4] = {Ah, Al, Bh, Bl};
    #pragma unroll
    for (int w = 0; w < 4; w++) {
        const __nv_bfloat16* g = ptrs[w] + gbase;
        const uint32_t s = sbase + SOFF(st, w);
        CP16(s,      g);
        CP16(s + 16, g + 8);
    }
}

template<int EPI>
__global__ __launch_bounds__(256, 2) void gemm_bf16_pipe(
    const __nv_bfloat16* __restrict__ Ah, const __nv_bfloat16* __restrict__ Al,
    const __nv_bfloat16* __restrict__ Bh, const __nv_bfloat16* __restrict__ Bl,
    const float* __restrict__ bias, const float* __restrict__ res,
    float* __restrict__ C, __nv_bfloat16* __restrict__ Ch,
    __nv_bfloat16* __restrict__ Cl, int M, int N, int K)
{
    extern __shared__ char smemc[];
    const uint32_t sb = smem_to_u32(smemc);

    const int tid    = threadIdx.x;
    const int wid    = tid >> 5, lane = tid & 31;
    const int warp_m = wid & 3;
    const int warp_n = wid >> 2;
    const int brow   = blockIdx.y * 128;
    const int bcol   = blockIdx.x * 128;

    const __nv_bfloat16* Agh = Ah + (size_t)brow * K;
    const __nv_bfloat16* Agl = Al + (size_t)brow * K;
    const __nv_bfloat16* Bgh = Bh + (size_t)bcol * K;
    const __nv_bfloat16* Bgl = Bl + (size_t)bcol * K;

    float acc[64];
    #pragma unroll
    for (int i = 0; i < 64; i++) acc[i] = 0.f;

    const int NKB = K >> 5;

    // prologue: fill both stages
    stage_load(sb, 0, Agh, Agl, Bgh, Bgl, 0, tid, K);
    CP_COMMIT();
    stage_load(sb, 1, Agh, Agl, Bgh, Bgl, 1, tid, K);
    CP_COMMIT();

    // ldmatrix per-lane offsets (within a tile)
    const int a_row = warp_m * 32 + (lane & 7) + ((lane >> 3) & 1) * 8;
    const uint32_t a_off = (uint32_t)(a_row * PITCH + (lane >> 4) * 16);
    const int b_row = warp_n * 64 + (lane & 7) + (lane >> 4) * 8;
    const uint32_t b_off = (uint32_t)(b_row * PITCH + ((lane >> 3) & 1) * 16);

    for (int kb = 0; kb < NKB; kb++) {
        CP_WAIT1();                 // stage kb complete (kb+1 may be in flight)
        __syncthreads();

        const int st = kb & 1;
        const uint32_t sAh = sb + SOFF(st,0), sAl = sb + SOFF(st,1);
        const uint32_t sBh = sb + SOFF(st,2), sBl = sb + SOFF(st,3);

        #pragma unroll
        for (int k16 = 0; k16 < 2; k16++) {
            uint32_t ah[2][4], al[2][4];
            #pragma unroll
            for (int mt = 0; mt < 2; mt++) {
                const uint32_t off = a_off + mt * 16 * PITCH + k16 * 32;
                ldsm_x4(ah[mt], sAh + off);
                ldsm_x4(al[mt], sAl + off);
            }
            #pragma unroll
            for (int nt = 0; nt < 4; nt++) {
                uint32_t bh[4], bl[4];
                const uint32_t off = b_off + nt * 16 * PITCH + k16 * 32;
                ldsm_x4(bh, sBh + off);
                ldsm_x4(bl, sBl + off);
                #pragma unroll
                for (int mt = 0; mt < 2; mt++)
                    #pragma unroll
                    for (int t = 0; t < 2; t++)
                        mma_bf16(&acc[(mt*8 + nt*2 + t)*4], ah[mt], &bl[t*2]);
                #pragma unroll
                for (int mt = 0; mt < 2; mt++)
                    #pragma unroll
                    for (int t = 0; t < 2; t++)
                        mma_bf16(&acc[(mt*8 + nt*2 + t)*4], al[mt], &bh[t*2]);
                #pragma unroll
                for (int mt = 0; mt < 2; mt++)
                    #pragma unroll
                    for (int t = 0; t < 2; t++)
                        mma_bf16(&acc[(mt*8 + nt*2 + t)*4], ah[mt], &bh[t*2]);
            }
        }
        __syncthreads();            // all warps done reading stage kb

        if (kb + 2 < NKB) {         // refill the buffer just freed
            stage_load(sb, st, Agh, Agl, Bgh, Bgl, kb + 2, tid, K);
            CP_COMMIT();
        }
    }

    // ---------------- epilogue ----------------
    const int erow = brow + warp_m * 32 + (lane >> 2);
    const int ecol = bcol + warp_n * 64 + (lane & 3) * 2;
    #pragma unroll
    for (int mt = 0; mt < 2; mt++) {
        #pragma unroll
        for (int j = 0; j < 8; j++) {
            const float* c = &acc[(mt*8 + j)*4];
            const int grow = erow + mt * 16;
            const int gcol = ecol + j * 8;
            float2 bvv = *(const float2*)(bias + gcol);
            float o0x = c[0] + bvv.x, o0y = c[1] + bvv.y;
            float o1x = c[2] + bvv.x, o1y = c[3] + bvv.y;
            if (EPI == 1) {
                float2 r0v = *(const float2*)(res + (size_t)grow * N + gcol);
                float2 r1v = *(const float2*)(res + (size_t)(grow+8) * N + gcol);
                o0x += r0v.x; o0y += r0v.y;
                o1x += r1v.x; o1y += r1v.y;
            }
            if (EPI == 2) {
                o0x = gelu_exact(o0x); o0y = gelu_exact(o0y);
                o1x = gelu_exact(o1x); o1y = gelu_exact(o1y);
                split_store2(Ch, Cl, (size_t)grow * N + gcol,     o0x, o0y);
                split_store2(Ch, Cl, (size_t)(grow+8) * N + gcol, o1x, o1y);
            } else {
                *(float2*)(C + (size_t)grow * N + gcol)     = make_float2(o0x, o0y);
                *(float2*)(C + (size_t)(grow+8) * N + gcol) = make_float2(o1x, o1y);
            }
        }
    }
}

// --------------------------- Flash attention --------------------------------
// Reads q/k/v from fused qkv buffer (row stride QKVN), writes ctx hi/lo bf16.
__global__ __launch_bounds__(64) void flash_kernel(
    const float* __restrict__ QKV, __nv_bfloat16* __restrict__ Oh,
    __nv_bfloat16* __restrict__ Ol)
{
    __shared__ float Ks[32][64];
    __shared__ float Vs[32][64];
    __shared__ float Ss[32][64];

    const int qt  = blockIdx.x;
    const int bh  = blockIdx.y;
    const int b   = bh >> 4;
    const int hh  = bh & 15;
    const int tid = threadIdx.x;
    const int qrow = qt * 64 + tid;

    const size_t qbase = ((size_t)b * TT) * QKVN + (size_t)hh * DD;
    const float* Qp = QKV + qbase;
    const float* Kp = QKV + qbase + 1024;
    const float* Vp = QKV + qbase + 2048;

    float4 q4[16], o4[16];
    {
        const float4* qp = (const float4*)(Qp + (size_t)qrow * QKVN);
        #pragma unroll
        for (int i = 0; i < 16; i++) {
            q4[i] = qp[i];
            o4[i] = make_float4(0.f, 0.f, 0.f, 0.f);
        }
    }
    float m = -INFINITY, l = 0.f;

    const int nkt = 2 * qt + 2;
    for (int kt = 0; kt < nkt; kt++) {
        const float* kbase = Kp + (size_t)(kt * 32) * QKVN;
        const float* vbase = Vp + (size_t)(kt * 32) * QKVN;
        #pragma unroll
        for (int i = 0; i < 8; i++) {
            int p = i * 64 + tid;
            int r = p >> 4, c = p & 15;
            ((float4*)&Ks[r][0])[c] = ((const float4*)(kbase + (size_t)r * QKVN))[c];
            ((float4*)&Vs[r][0])[c] = ((const float4*)(vbase + (size_t)r * QKVN))[c];
        }
        __syncthreads();

        int jhi = qrow - kt * 32 + 1;
        if (jhi > 32) jhi = 32;
        if (jhi > 0) {
            float tmax = -INFINITY;
            #pragma unroll 2
            for (int j = 0; j < jhi; j++) {
                float4 a = make_float4(0.f, 0.f, 0.f, 0.f);
                #pragma unroll
                for (int i = 0; i < 16; i++) {
                    float4 kv = ((const float4*)&Ks[j][0])[i];
                    a.x = fmaf(q4[i].x, kv.x, a.x);
                    a.y = fmaf(q4[i].y, kv.y, a.y);
                    a.z = fmaf(q4[i].z, kv.z, a.z);
                    a.w = fmaf(q4[i].w, kv.w, a.w);
                }
                float sj = ((a.x + a.y) + (a.z + a.w)) * 0.125f;
                Ss[j][tid] = sj;
                tmax = fmaxf(tmax, sj);
            }
            float mnew  = fmaxf(m, tmax);
            float alpha = __expf(m - mnew);
            l *= alpha;
            #pragma unroll
            for (int i = 0; i < 16; i++) {
                o4[i].x *= alpha; o4[i].y *= alpha;
                o4[i].z *= alpha; o4[i].w *= alpha;
            }
            #pragma unroll 2
            for (int j = 0; j < jhi; j++) {
                float p = __expf(Ss[j][tid] - mnew);
                l += p;
                #pragma unroll
                for (int i = 0; i < 16; i++) {
                    float4 vv = ((const float4*)&Vs[j][0])[i];
                    o4[i].x = fmaf(p, vv.x, o4[i].x);
                    o4[i].y = fmaf(p, vv.y, o4[i].y);
                    o4[i].z = fmaf(p, vv.z, o4[i].z);
                    o4[i].w = fmaf(p, vv.w, o4[i].w);
                }
            }
            m = mnew;
        }
        __syncthreads();
    }

    const float inv = 1.f / l;
    const size_t obase = ((size_t)b * TT) * CC + (size_t)hh * DD
                       + (size_t)qrow * CC;
    #pragma unroll
    for (int i = 0; i < 16; i++) {
        split_store2(Oh, Ol, obase + i*4,     o4[i].x * inv, o4[i].y * inv);
        split_store2(Oh, Ol, obase + i*4 + 2, o4[i].z * inv, o4[i].w * inv);
    }
}

// ------------------------------ launch --------------------------------------
extern "C" void kernel_launch(void* const* d_in, const int* in_sizes, int n_in,
                              void* d_out, int out_size)
{
    (void)in_sizes; (void)n_in; (void)out_size;
    const float* x    = (const float*)d_in[0];
    const float* ln1w = (const float*)d_in[2];
    const float* ln1b = (const float*)d_in[3];
    const float* ln2w = (const float*)d_in[4];
    const float* ln2b = (const float*)d_in[5];
    const float* wq   = (const float*)d_in[6];
    const float* bq   = (const float*)d_in[7];
    const float* wk   = (const float*)d_in[8];
    const float* bk   = (const float*)d_in[9];
    const float* wv   = (const float*)d_in[10];
    const float* bv   = (const float*)d_in[11];
    const float* wo   = (const float*)d_in[12];
    const float* bo   = (const float*)d_in[13];
    const float* w1   = (const float*)d_in[14];
    const float* b1   = (const float*)d_in[15];
    const float* w2   = (const float*)d_in[16];
    const float* b2   = (const float*)d_in[17];
    float* out = (float*)d_out;

    __nv_bfloat16 *hh, *hl, *ctxh, *ctxl, *ffh, *ffl;
    __nv_bfloat16 *wqkvTh, *wqkvTl, *woTh, *woTl, *w1Th, *w1Tl, *w2Th, *w2Tl;
    float *qkv, *x2, *bqkv;
    cudaGetSymbolAddress((void**)&hh,   g_hh);
    cudaGetSymbolAddress((void**)&hl,   g_hl);
    cudaGetSymbolAddress((void**)&ctxh, g_ctxh);
    cudaGetSymbolAddress((void**)&ctxl, g_ctxl);
    cudaGetSymbolAddress((void**)&ffh,  g_ffh);
    cudaGetSymbolAddress((void**)&ffl,  g_ffl);
    cudaGetSymbolAddress((void**)&qkv,  g_qkv);
    cudaGetSymbolAddress((void**)&x2,   g_x2);
    cudaGetSymbolAddress((void**)&bqkv, g_bqkv);
    cudaGetSymbolAddress((void**)&wqkvTh, g_wqkvTh);
    cudaGetSymbolAddress((void**)&wqkvTl, g_wqkvTl);
    cudaGetSymbolAddress((void**)&woTh, g_woTh);
    cudaGetSymbolAddress((void**)&woTl, g_woTl);
    cudaGetSymbolAddress((void**)&w1Th, g_w1Th);
    cudaGetSymbolAddress((void**)&w1Tl, g_w1Tl);
    cudaGetSymbolAddress((void**)&w2Th, g_w2Th);
    cudaGetSymbolAddress((void**)&w2Tl, g_w2Tl);

    cudaFuncSetAttribute(gemm_bf16_pipe<0>, cudaFuncAttributeMaxDynamicSharedMemorySize, GEMM_SMEM);
    cudaFuncSetAttribute(gemm_bf16_pipe<1>, cudaFuncAttributeMaxDynamicSharedMemorySize, GEMM_SMEM);
    cudaFuncSetAttribute(gemm_bf16_pipe<2>, cudaFuncAttributeMaxDynamicSharedMemorySize, GEMM_SMEM);

    const dim3 tB(32, 8);
    // fused QKV weight: rows 0..1023 = wq^T, 1024..2047 = wk^T, 2048..3071 = wv^T
    transpose_split_kernel<<<dim3(CC/32,  CC/32),  tB>>>(wq, wqkvTh,           wqkvTl,           CC,  CC);
    transpose_split_kernel<<<dim3(CC/32,  CC/32),  tB>>>(wk, wqkvTh + 1024*CC, wqkvTl + 1024*CC, CC,  CC);
    transpose_split_kernel<<<dim3(CC/32,  CC/32),  tB>>>(wv, wqkvTh + 2048*CC, wqkvTl + 2048*CC, CC,  CC);
    transpose_split_kernel<<<dim3(CC/32,  CC/32),  tB>>>(wo, woTh, woTl, CC,  CC);
    transpose_split_kernel<<<dim3(FFN/32, CC/32),  tB>>>(w1, w1Th, w1Tl, CC,  FFN);
    transpose_split_kernel<<<dim3(CC/32,  FFN/32), tB>>>(w2, w2Th, w2Tl, FFN, CC);
    bias_concat_kernel<<<12, 256>>>(bq, bk, bv, bqkv);

    const dim3 gQKV(QKVN / 128, NROWS / 128);   // 24 x 64
    const dim3 gC  (CC   / 128, NROWS / 128);   // 8 x 64
    const dim3 gF  (FFN  / 128, NROWS / 128);   // 32 x 64

    // 1. h = LN1(x)  (bf16 hi/lo)
    ln_split_kernel<<<NROWS, 256>>>(x, ln1w, ln1b, hh, hl);
    // 2. qkv = h@Wqkv + bqkv  (fused, fp32 out)
    gemm_bf16_pipe<0><<<gQKV, 256, GEMM_SMEM>>>(hh, hl, wqkvTh, wqkvTl, bqkv,
                                                nullptr, qkv, nullptr, nullptr,
                                                NROWS, QKVN, CC);
    // 3. ctx = causal-softmax(qk^T/8) v  (bf16 hi/lo out)
    flash_kernel<<<dim3(TT / 64, BB * HHD), 64>>>(qkv, ctxh, ctxl);
    // 4. x2 = x + ctx@wo + bo
    gemm_bf16_pipe<1><<<gC, 256, GEMM_SMEM>>>(ctxh, ctxl, woTh, woTl, bo, x,
                                              x2, nullptr, nullptr,
                                              NROWS, CC, CC);
    // 5. h = LN2(x2)  (bf16 hi/lo)
    ln_split_kernel<<<NROWS, 256>>>(x2, ln2w, ln2b, hh, hl);
    // 6. ff = gelu(h@w1 + b1)  (bf16 hi/lo out)
    gemm_bf16_pipe<2><<<gF, 256, GEMM_SMEM>>>(hh, hl, w1Th, w1Tl, b1, nullptr,
                                              nullptr, ffh, ffl,
                                              NROWS, FFN, CC);
    // 7. out = x2 + ff@w2 + b2
    gemm_bf16_pipe<1><<<gC, 256, GEMM_SMEM>>>(ffh, ffl, w2Th, w2Tl, b2, x2,
                                              out, nullptr, nullptr,
                                              NROWS, CC, FFN);
}

// round 11
// speedup vs baseline: 1.4064x; 1.2628x over previous
#include <cuda_runtime.h>
#include <cuda_fp16.h>
#include <math.h>
#include <stdint.h>

// Problem constants
#define BB   8
#define TT   1024
#define CC   1024
#define HHD  16
#define DD   64
#define NROWS (BB*TT)      // 8192
#define FFN   (4*CC)       // 4096
#define QKVN 3072
#define EPS  1e-5f

// -------------------- scratch (static device memory; no allocs) ------------
// fp16 hi/lo activations
__device__ __half g_hh [(size_t)NROWS*CC];
__device__ __half g_hl [(size_t)NROWS*CC];
__device__ __half g_ctxh[(size_t)NROWS*CC];
__device__ __half g_ctxl[(size_t)NROWS*CC];
__device__ __half g_ffh[(size_t)NROWS*FFN];
__device__ __half g_ffl[(size_t)NROWS*FFN];
// fp32 buffers
__device__ float g_qkv[(size_t)NROWS*QKVN];
__device__ float g_x2 [(size_t)NROWS*CC];
// fp16 transposed weights [N][K] K-major (single precision term)
__device__ __half g_wqkvT[(size_t)QKVN*CC];
__device__ __half g_woT[(size_t)CC*CC];
__device__ __half g_w1T[(size_t)FFN*CC];
__device__ __half g_w2T[(size_t)CC*FFN];
__device__ float g_bqkv[QKVN];

// ---------------------------- helpers ---------------------------------------
__device__ __forceinline__ uint32_t smem_to_u32(const void* p) {
    uint32_t a;
    asm("{ .reg .u64 t; cvta.to.shared.u64 t, %1; cvt.u32.u64 %0, t; }"
        : "=r"(a) : "l"(p));
    return a;
}
__device__ __forceinline__ void ldsm_x4(uint32_t* r, uint32_t addr) {
    asm volatile("ldmatrix.sync.aligned.m8n8.x4.shared.b16 {%0,%1,%2,%3}, [%4];"
                 : "=r"(r[0]), "=r"(r[1]), "=r"(r[2]), "=r"(r[3]) : "r"(addr));
}
__device__ __forceinline__ void mma_f16(float* c, const uint32_t* a,
                                        const uint32_t* b) {
    asm volatile(
        "mma.sync.aligned.m16n8k16.row.col.f32.f16.f16.f32 "
        "{%0,%1,%2,%3}, {%4,%5,%6,%7}, {%8,%9}, {%0,%1,%2,%3};"
        : "+f"(c[0]), "+f"(c[1]), "+f"(c[2]), "+f"(c[3])
        : "r"(a[0]), "r"(a[1]), "r"(a[2]), "r"(a[3]), "r"(b[0]), "r"(b[1]));
}
#define CP16(sa, gp) \
    asm volatile("cp.async.cg.shared.global [%0], [%1], 16;" \
                 :: "r"(sa), "l"(gp) : "memory")
#define CP_COMMIT() asm volatile("cp.async.commit_group;" ::: "memory")
#define CP_WAIT1()  asm volatile("cp.async.wait_group 1;" ::: "memory")

__device__ __forceinline__ float gelu_exact(float v) {
    return 0.5f * v * (1.0f + erff(v * 0.70710678118654752f));
}
// split a float pair into fp16 hi/lo pairs and store
__device__ __forceinline__ void split_store2(__half* Ch, __half* Cl,
                                             size_t off, float x, float y) {
    __half2 h, l;
    h.x = __float2half_rn(x); h.y = __float2half_rn(y);
    l.x = __float2half_rn(x - __half2float(h.x));
    l.y = __float2half_rn(y - __half2float(h.y));
    *(__half2*)(Ch + off) = h;
    *(__half2*)(Cl + off) = l;
}

// --------------------------- weight transpose (fp16) ------------------------
// WT[n][k] = fp16(W[k][n])
__global__ __launch_bounds__(256) void transpose_h_kernel(
    const float* __restrict__ W, __half* __restrict__ WT, int K, int N)
{
    __shared__ float t[32][33];
    const int n0 = blockIdx.x * 32, k0 = blockIdx.y * 32;
    const int tx = threadIdx.x, ty = threadIdx.y;
    #pragma unroll
    for (int i = 0; i < 32; i += 8)
        t[ty + i][tx] = W[(size_t)(k0 + ty + i) * N + n0 + tx];
    __syncthreads();
    #pragma unroll
    for (int i = 0; i < 32; i += 8)
        WT[(size_t)(n0 + ty + i) * K + k0 + tx] = __float2half_rn(t[tx][ty + i]);
}

__global__ void bias_concat_kernel(const float* bq, const float* bk,
                                   const float* bv, float* out)
{
    int i = blockIdx.x * blockDim.x + threadIdx.x;
    if (i < 1024)       out[i] = bq[i];
    else if (i < 2048)  out[i] = bk[i - 1024];
    else if (i < 3072)  out[i] = bv[i - 2048];
}

// ---------------------------- LayerNorm (split fp16 out) --------------------
__global__ __launch_bounds__(256) void ln_split_kernel(
    const float* __restrict__ x, const float* __restrict__ w,
    const float* __restrict__ b, __half* __restrict__ outh,
    __half* __restrict__ outl)
{
    const int row = blockIdx.x;
    const int tid = threadIdx.x;
    const float4* xr = (const float4*)(x + (size_t)row * CC);
    float4 v = xr[tid];
    float s  = v.x + v.y + v.z + v.w;
    float ss = v.x*v.x + v.y*v.y + v.z*v.z + v.w*v.w;

    __shared__ float red0[8], red1[8];
    #pragma unroll
    for (int o = 16; o > 0; o >>= 1) {
        s  += __shfl_down_sync(0xffffffffu, s,  o);
        ss += __shfl_down_sync(0xffffffffu, ss, o);
    }
    const int wid = tid >> 5, lid = tid & 31;
    if (lid == 0) { red0[wid] = s; red1[wid] = ss; }
    __syncthreads();
    if (tid == 0) {
        float S = 0.f, SS = 0.f;
        #pragma unroll
        for (int i = 0; i < 8; i++) { S += red0[i]; SS += red1[i]; }
        float mu  = S * (1.f / CC);
        float var = SS * (1.f / CC) - mu * mu;
        red0[0] = mu;
        red1[0] = rsqrtf(var + EPS);
    }
    __syncthreads();
    const float mu = red0[0], rstd = red1[0];
    float4 wv = ((const float4*)w)[tid];
    float4 bv = ((const float4*)b)[tid];
    float ox = (v.x - mu) * rstd * wv.x + bv.x;
    float oy = (v.y - mu) * rstd * wv.y + bv.y;
    float oz = (v.z - mu) * rstd * wv.z + bv.z;
    float ow = (v.w - mu) * rstd * wv.w + bv.w;
    const size_t off = (size_t)row * CC + tid * 4;
    split_store2(outh, outl, off,     ox, oy);
    split_store2(outh, outl, off + 2, oz, ow);
}

// --------------------- fp16x2 cp.async pipelined GEMM -----------------------
// C[M,N] = epilogue(A[M,K] @ BT[N,K]^T + bias, res)
// A pre-split fp16 hi/lo (Ah+Al ~ fp32); B single fp16.
// D = Ah*B + Al*B  (2 MMAs per tile; error = B rounding ~1.5e-4 RMS)
// EPI 0: C=+bias(fp32)  EPI 1: C=+bias+res(fp32)  EPI 2: Ch/Cl=split(gelu(+bias))
// CTA 128x128x32, 256 thr, warps 4(m) x 2(n); 3-stage cp.async, 2 CTAs/SM.

#define PITCH      80
#define TILE_B     (128 * PITCH)               // 10240
#define SOFF(st,w) (((st)*3 + (w)) * TILE_B)   // w: 0=Ah 1=Al 2=B
#define GEMM_SMEM  (9 * TILE_B)                // 92160 (3 stages x 3 tiles)

__device__ __forceinline__ void stage_load(
    uint32_t sb, int st,
    const __half* Ah, const __half* Al, const __half* Bh,
    int kb, int tid, int K)
{
    const int r  = tid >> 1;               // 0..127
    const int c0 = (tid & 1) * 2;          // 16B chunk 0/2
    const size_t gbase = (size_t)r * K + (size_t)kb * 32 + c0 * 8;
    const uint32_t sbase = sb + (uint32_t)(r * PITCH + c0 * 16);
    const __half* ptrs[3] = {Ah, Al, Bh};
    #pragma unroll
    for (int w = 0; w < 3; w++) {
        const __half* g = ptrs[w] + gbase;
        const uint32_t s = sbase + SOFF(st, w);
        CP16(s,      g);
        CP16(s + 16, g + 8);
    }
}

template<int EPI>
__global__ __launch_bounds__(256, 2) void gemm_f16_pipe(
    const __half* __restrict__ Ah, const __half* __restrict__ Al,
    const __half* __restrict__ Bh,
    const float* __restrict__ bias, const float* __restrict__ res,
    float* __restrict__ C, __half* __restrict__ Ch,
    __half* __restrict__ Cl, int M, int N, int K)
{
    extern __shared__ char smemc[];
    const uint32_t sb = smem_to_u32(smemc);

    const int tid    = threadIdx.x;
    const int wid    = tid >> 5, lane = tid & 31;
    const int warp_m = wid & 3;
    const int warp_n = wid >> 2;
    const int brow   = blockIdx.y * 128;
    const int bcol   = blockIdx.x * 128;

    const __half* Agh = Ah + (size_t)brow * K;
    const __half* Agl = Al + (size_t)brow * K;
    const __half* Bg  = Bh + (size_t)bcol * K;

    float acc[64];
    #pragma unroll
    for (int i = 0; i < 64; i++) acc[i] = 0.f;

    const int NKB = K >> 5;

    // prologue: fill stages 0,1
    stage_load(sb, 0, Agh, Agl, Bg, 0, tid, K);
    CP_COMMIT();
    stage_load(sb, 1, Agh, Agl, Bg, 1, tid, K);
    CP_COMMIT();

    // ldmatrix per-lane offsets (within a tile)
    const int a_row = warp_m * 32 + (lane & 7) + ((lane >> 3) & 1) * 8;
    const uint32_t a_off = (uint32_t)(a_row * PITCH + (lane >> 4) * 16);
    const int b_row = warp_n * 64 + (lane & 7) + (lane >> 4) * 8;
    const uint32_t b_off = (uint32_t)(b_row * PITCH + ((lane >> 3) & 1) * 16);

    for (int kb = 0; kb < NKB; kb++) {
        CP_WAIT1();                 // stage kb ready (kb+1 may be in flight)
        __syncthreads();            // also: all warps done with stage kb-1

        if (kb + 2 < NKB) {         // refill buffer freed at kb-1
            stage_load(sb, (kb + 2) % 3, Agh, Agl, Bg, kb + 2, tid, K);
        }
        CP_COMMIT();

        const int st = kb % 3;
        const uint32_t sAh = sb + SOFF(st,0);
        const uint32_t sAl = sb + SOFF(st,1);
        const uint32_t sB  = sb + SOFF(st,2);

        #pragma unroll
        for (int k16 = 0; k16 < 2; k16++) {
            uint32_t ah[2][4], al[2][4];
            #pragma unroll
            for (int mt = 0; mt < 2; mt++) {
                const uint32_t off = a_off + mt * 16 * PITCH + k16 * 32;
                ldsm_x4(ah[mt], sAh + off);
                ldsm_x4(al[mt], sAl + off);
            }
            #pragma unroll
            for (int nt = 0; nt < 4; nt++) {
                uint32_t bh[4];
                ldsm_x4(bh, sB + b_off + nt * 16 * PITCH + k16 * 32);
                #pragma unroll
                for (int mt = 0; mt < 2; mt++)
                    #pragma unroll
                    for (int t = 0; t < 2; t++)
                        mma_f16(&acc[(mt*8 + nt*2 + t)*4], ah[mt], &bh[t*2]);
                #pragma unroll
                for (int mt = 0; mt < 2; mt++)
                    #pragma unroll
                    for (int t = 0; t < 2; t++)
                        mma_f16(&acc[(mt*8 + nt*2 + t)*4], al[mt], &bh[t*2]);
            }
        }
    }

    __syncthreads();

    // ---------------- epilogue ----------------
    const int erow = brow + warp_m * 32 + (lane >> 2);
    const int ecol = bcol + warp_n * 64 + (lane & 3) * 2;
    #pragma unroll
    for (int mt = 0; mt < 2; mt++) {
        #pragma unroll
        for (int j = 0; j < 8; j++) {
            const float* c = &acc[(mt*8 + j)*4];
            const int grow = erow + mt * 16;
            const int gcol = ecol + j * 8;
            float2 bvv = *(const float2*)(bias + gcol);
            float o0x = c[0] + bvv.x, o0y = c[1] + bvv.y;
            float o1x = c[2] + bvv.x, o1y = c[3] + bvv.y;
            if (EPI == 1) {
                float2 r0v = *(const float2*)(res + (size_t)grow * N + gcol);
                float2 r1v = *(const float2*)(res + (size_t)(grow+8) * N + gcol);
                o0x += r0v.x; o0y += r0v.y;
                o1x += r1v.x; o1y += r1v.y;
            }
            if (EPI == 2) {
                o0x = gelu_exact(o0x); o0y = gelu_exact(o0y);
                o1x = gelu_exact(o1x); o1y = gelu_exact(o1y);
                split_store2(Ch, Cl, (size_t)grow * N + gcol,     o0x, o0y);
                split_store2(Ch, Cl, (size_t)(grow+8) * N + gcol, o1x, o1y);
            } else {
                *(float2*)(C + (size_t)grow * N + gcol)     = make_float2(o0x, o0y);
                *(float2*)(C + (size_t)(grow+8) * N + gcol) = make_float2(o1x, o1y);
            }
        }
    }
}

// --------------------------- Flash attention --------------------------------
// Reads q/k/v from fused qkv buffer (row stride QKVN), writes ctx hi/lo fp16.
__global__ __launch_bounds__(64) void flash_kernel(
    const float* __restrict__ QKV, __half* __restrict__ Oh,
    __half* __restrict__ Ol)
{
    __shared__ float Ks[32][64];
    __shared__ float Vs[32][64];
    __shared__ float Ss[32][64];

    const int qt  = blockIdx.x;
    const int bh  = blockIdx.y;
    const int b   = bh >> 4;
    const int hh  = bh & 15;
    const int tid = threadIdx.x;
    const int qrow = qt * 64 + tid;

    const size_t qbase = ((size_t)b * TT) * QKVN + (size_t)hh * DD;
    const float* Qp = QKV + qbase;
    const float* Kp = QKV + qbase + 1024;
    const float* Vp = QKV + qbase + 2048;

    float4 q4[16], o4[16];
    {
        const float4* qp = (const float4*)(Qp + (size_t)qrow * QKVN);
        #pragma unroll
        for (int i = 0; i < 16; i++) {
            q4[i] = qp[i];
            o4[i] = make_float4(0.f, 0.f, 0.f, 0.f);
        }
    }
    float m = -INFINITY, l = 0.f;

    const int nkt = 2 * qt + 2;
    for (int kt = 0; kt < nkt; kt++) {
        const float* kbase = Kp + (size_t)(kt * 32) * QKVN;
        const float* vbase = Vp + (size_t)(kt * 32) * QKVN;
        #pragma unroll
        for (int i = 0; i < 8; i++) {
            int p = i * 64 + tid;
            int r = p >> 4, c = p & 15;
            ((float4*)&Ks[r][0])[c] = ((const float4*)(kbase + (size_t)r * QKVN))[c];
            ((float4*)&Vs[r][0])[c] = ((const float4*)(vbase + (size_t)r * QKVN))[c];
        }
        __syncthreads();

        int jhi = qrow - kt * 32 + 1;
        if (jhi > 32) jhi = 32;
        if (jhi > 0) {
            float tmax = -INFINITY;
            #pragma unroll 2
            for (int j = 0; j < jhi; j++) {
                float4 a = make_float4(0.f, 0.f, 0.f, 0.f);
                #pragma unroll
                for (int i = 0; i < 16; i++) {
                    float4 kv = ((const float4*)&Ks[j][0])[i];
                    a.x = fmaf(q4[i].x, kv.x, a.x);
                    a.y = fmaf(q4[i].y, kv.y, a.y);
                    a.z = fmaf(q4[i].z, kv.z, a.z);
                    a.w = fmaf(q4[i].w, kv.w, a.w);
                }
                float sj = ((a.x + a.y) + (a.z + a.w)) * 0.125f;
                Ss[j][tid] = sj;
                tmax = fmaxf(tmax, sj);
            }
            float mnew  = fmaxf(m, tmax);
            float alpha = __expf(m - mnew);
            l *= alpha;
            #pragma unroll
            for (int i = 0; i < 16; i++) {
                o4[i].x *= alpha; o4[i].y *= alpha;
                o4[i].z *= alpha; o4[i].w *= alpha;
            }
            #pragma unroll 2
            for (int j = 0; j < jhi; j++) {
                float p = __expf(Ss[j][tid] - mnew);
                l += p;
                #pragma unroll
                for (int i = 0; i < 16; i++) {
                    float4 vv = ((const float4*)&Vs[j][0])[i];
                    o4[i].x = fmaf(p, vv.x, o4[i].x);
                    o4[i].y = fmaf(p, vv.y, o4[i].y);
                    o4[i].z = fmaf(p, vv.z, o4[i].z);
                    o4[i].w = fmaf(p, vv.w, o4[i].w);
                }
            }
            m = mnew;
        }
        __syncthreads();
    }

    const float inv = 1.f / l;
    const size_t obase = ((size_t)b * TT) * CC + (size_t)hh * DD
                       + (size_t)qrow * CC;
    #pragma unroll
    for (int i = 0; i < 16; i++) {
        split_store2(Oh, Ol, obase + i*4,     o4[i].x * inv, o4[i].y * inv);
        split_store2(Oh, Ol, obase + i*4 + 2, o4[i].z * inv, o4[i].w * inv);
    }
}

// ------------------------------ launch --------------------------------------
extern "C" void kernel_launch(void* const* d_in, const int* in_sizes, int n_in,
                              void* d_out, int out_size)
{
    (void)in_sizes; (void)n_in; (void)out_size;
    const float* x    = (const float*)d_in[0];
    const float* ln1w = (const float*)d_in[2];
    const float* ln1b = (const float*)d_in[3];
    const float* ln2w = (const float*)d_in[4];
    const float* ln2b = (const float*)d_in[5];
    const float* wq   = (const float*)d_in[6];
    const float* bq   = (const float*)d_in[7];
    const float* wk   = (const float*)d_in[8];
    const float* bk   = (const float*)d_in[9];
    const float* wv   = (const float*)d_in[10];
    const float* bv   = (const float*)d_in[11];
    const float* wo   = (const float*)d_in[12];
    const float* bo   = (const float*)d_in[13];
    const float* w1   = (const float*)d_in[14];
    const float* b1   = (const float*)d_in[15];
    const float* w2   = (const float*)d_in[16];
    const float* b2   = (const float*)d_in[17];
    float* out = (float*)d_out;

    __half *hh, *hl, *ctxh, *ctxl, *ffh, *ffl;
    __half *wqkvT, *woT, *w1T, *w2T;
    float *qkv, *x2, *bqkv;
    cudaGetSymbolAddress((void**)&hh,   g_hh);
    cudaGetSymbolAddress((void**)&hl,   g_hl);
    cudaGetSymbolAddress((void**)&ctxh, g_ctxh);
    cudaGetSymbolAddress((void**)&ctxl, g_ctxl);
    cudaGetSymbolAddress((void**)&ffh,  g_ffh);
    cudaGetSymbolAddress((void**)&ffl,  g_ffl);
    cudaGetSymbolAddress((void**)&qkv,  g_qkv);
    cudaGetSymbolAddress((void**)&x2,   g_x2);
    cudaGetSymbolAddress((void**)&bqkv, g_bqkv);
    cudaGetSymbolAddress((void**)&wqkvT, g_wqkvT);
    cudaGetSymbolAddress((void**)&woT, g_woT);
    cudaGetSymbolAddress((void**)&w1T, g_w1T);
    cudaGetSymbolAddress((void**)&w2T, g_w2T);

    cudaFuncSetAttribute(gemm_f16_pipe<0>, cudaFuncAttributeMaxDynamicSharedMemorySize, GEMM_SMEM);
    cudaFuncSetAttribute(gemm_f16_pipe<1>, cudaFuncAttributeMaxDynamicSharedMemorySize, GEMM_SMEM);
    cudaFuncSetAttribute(gemm_f16_pipe<2>, cudaFuncAttributeMaxDynamicSharedMemorySize, GEMM_SMEM);

    const dim3 tB(32, 8);
    // fused QKV weight: rows 0..1023 = wq^T, 1024..2047 = wk^T, 2048..3071 = wv^T
    transpose_h_kernel<<<dim3(CC/32,  CC/32),  tB>>>(wq, wqkvT,           CC,  CC);
    transpose_h_kernel<<<dim3(CC/32,  CC/32),  tB>>>(wk, wqkvT + 1024*CC, CC,  CC);
    transpose_h_kernel<<<dim3(CC/32,  CC/32),  tB>>>(wv, wqkvT + 2048*CC, CC,  CC);
    transpose_h_kernel<<<dim3(CC/32,  CC/32),  tB>>>(wo, woT, CC,  CC);
    transpose_h_kernel<<<dim3(FFN/32, CC/32),  tB>>>(w1, w1T, CC,  FFN);
    transpose_h_kernel<<<dim3(CC/32,  FFN/32), tB>>>(w2, w2T, FFN, CC);
    bias_concat_kernel<<<12, 256>>>(bq, bk, bv, bqkv);

    const dim3 gQKV(QKVN / 128, NROWS / 128);   // 24 x 64
    const dim3 gC  (CC   / 128, NROWS / 128);   // 8 x 64
    const dim3 gF  (FFN  / 128, NROWS / 128);   // 32 x 64

    // 1. h = LN1(x)  (fp16 hi/lo)
    ln_split_kernel<<<NROWS, 256>>>(x, ln1w, ln1b, hh, hl);
    // 2. qkv = h@Wqkv + bqkv  (fused, fp32 out)
    gemm_f16_pipe<0><<<gQKV, 256, GEMM_SMEM>>>(hh, hl, wqkvT, bqkv,
                                               nullptr, qkv, nullptr, nullptr,
                                               NROWS, QKVN, CC);
    // 3. ctx = causal-softmax(qk^T/8) v  (fp16 hi/lo out)
    flash_kernel<<<dim3(TT / 64, BB * HHD), 64>>>(qkv, ctxh, ctxl);
    // 4. x2 = x + ctx@wo + bo
    gemm_f16_pipe<1><<<gC, 256, GEMM_SMEM>>>(ctxh, ctxl, woT, bo, x,
                                             x2, nullptr, nullptr,
                                             NROWS, CC, CC);
    // 5. h = LN2(x2)  (fp16 hi/lo)
    ln_split_kernel<<<NROWS, 256>>>(x2, ln2w, ln2b, hh, hl);
    // 6. ff = gelu(h@w1 + b1)  (fp16 hi/lo out)
    gemm_f16_pipe<2><<<gF, 256, GEMM_SMEM>>>(hh, hl, w1T, b1, nullptr,
                                             nullptr, ffh, ffl,
                                             NROWS, FFN, CC);
    // 7. out = x2 + ff@w2 + b2
    gemm_f16_pipe<1><<<gC, 256, GEMM_SMEM>>>(ffh, ffl, w2T, b2, x2,
                                             out, nullptr, nullptr,
                                             NROWS, CC, FFN);
}

// round 14
// speedup vs baseline: 2.2534x; 1.6022x over previous
#include <cuda_runtime.h>
#include <cuda_fp16.h>
#include <math.h>
#include <stdint.h>

// Problem constants
#define BB   8
#define TT   1024
#define CC   1024
#define HHD  16
#define DD   64
#define NROWS (BB*TT)      // 8192
#define FFN   (4*CC)       // 4096
#define QKVN 3072
#define EPS  1e-5f

// -------------------- scratch (static device memory; no allocs) ------------
// fp16 hi/lo activations
__device__ __half g_hh [(size_t)NROWS*CC];
__device__ __half g_hl [(size_t)NROWS*CC];
__device__ __half g_ctxh[(size_t)NROWS*CC];
__device__ __half g_ctxl[(size_t)NROWS*CC];
__device__ __half g_ffh[(size_t)NROWS*FFN];
__device__ __half g_ffl[(size_t)NROWS*FFN];
__device__ __half g_qkvh[(size_t)NROWS*QKVN];
__device__ __half g_qkvl[(size_t)NROWS*QKVN];
// fp32 buffers
__device__ float g_x2 [(size_t)NROWS*CC];
// fp16 transposed weights [N][K] K-major (single precision term)
__device__ __half g_wqkvT[(size_t)QKVN*CC];
__device__ __half g_woT[(size_t)CC*CC];
__device__ __half g_w1T[(size_t)FFN*CC];
__device__ __half g_w2T[(size_t)CC*FFN];
__device__ float g_bqkv[QKVN];

// ---------------------------- helpers ---------------------------------------
__device__ __forceinline__ uint32_t smem_to_u32(const void* p) {
    uint32_t a;
    asm("{ .reg .u64 t; cvta.to.shared.u64 t, %1; cvt.u32.u64 %0, t; }"
        : "=r"(a) : "l"(p));
    return a;
}
__device__ __forceinline__ void ldsm_x4(uint32_t* r, uint32_t addr) {
    asm volatile("ldmatrix.sync.aligned.m8n8.x4.shared.b16 {%0,%1,%2,%3}, [%4];"
                 : "=r"(r[0]), "=r"(r[1]), "=r"(r[2]), "=r"(r[3]) : "r"(addr));
}
__device__ __forceinline__ void ldsm_x4_t(uint32_t* r, uint32_t addr) {
    asm volatile("ldmatrix.sync.aligned.m8n8.x4.trans.shared.b16 {%0,%1,%2,%3}, [%4];"
                 : "=r"(r[0]), "=r"(r[1]), "=r"(r[2]), "=r"(r[3]) : "r"(addr));
}
__device__ __forceinline__ void mma_f16(float* c, const uint32_t* a,
                                        const uint32_t* b) {
    asm volatile(
        "mma.sync.aligned.m16n8k16.row.col.f32.f16.f16.f32 "
        "{%0,%1,%2,%3}, {%4,%5,%6,%7}, {%8,%9}, {%0,%1,%2,%3};"
        : "+f"(c[0]), "+f"(c[1]), "+f"(c[2]), "+f"(c[3])
        : "r"(a[0]), "r"(a[1]), "r"(a[2]), "r"(a[3]), "r"(b[0]), "r"(b[1]));
}
#define CP16(sa, gp) \
    asm volatile("cp.async.cg.shared.global [%0], [%1], 16;" \
                 :: "r"(sa), "l"(gp) : "memory")
#define CP_COMMIT() asm volatile("cp.async.commit_group;" ::: "memory")
#define CP_WAIT1()  asm volatile("cp.async.wait_group 1;" ::: "memory")

__device__ __forceinline__ float gelu_exact(float v) {
    return 0.5f * v * (1.0f + erff(v * 0.70710678118654752f));
}
__device__ __forceinline__ void split_store2(__half* Ch, __half* Cl,
                                             size_t off, float x, float y) {
    __half2 h, l;
    h.x = __float2half_rn(x); h.y = __float2half_rn(y);
    l.x = __float2half_rn(x - __half2float(h.x));
    l.y = __float2half_rn(y - __half2float(h.y));
    *(__half2*)(Ch + off) = h;
    *(__half2*)(Cl + off) = l;
}
__device__ __forceinline__ uint32_t h2pack(float x, float y) {
    __half2 h = __floats2half2_rn(x, y);
    return *(uint32_t*)&h;
}

// --------------------------- weight transpose (fp16) ------------------------
__global__ __launch_bounds__(256) void transpose_h_kernel(
    const float* __restrict__ W, __half* __restrict__ WT, int K, int N)
{
    __shared__ float t[32][33];
    const int n0 = blockIdx.x * 32, k0 = blockIdx.y * 32;
    const int tx = threadIdx.x, ty = threadIdx.y;
    #pragma unroll
    for (int i = 0; i < 32; i += 8)
        t[ty + i][tx] = W[(size_t)(k0 + ty + i) * N + n0 + tx];
    __syncthreads();
    #pragma unroll
    for (int i = 0; i < 32; i += 8)
        WT[(size_t)(n0 + ty + i) * K + k0 + tx] = __float2half_rn(t[tx][ty + i]);
}

__global__ void bias_concat_kernel(const float* bq, const float* bk,
                                   const float* bv, float* out)
{
    int i = blockIdx.x * blockDim.x + threadIdx.x;
    if (i < 1024)       out[i] = bq[i];
    else if (i < 2048)  out[i] = bk[i - 1024];
    else if (i < 3072)  out[i] = bv[i - 2048];
}

// ---------------------------- LayerNorm (split fp16 out) --------------------
__global__ __launch_bounds__(256) void ln_split_kernel(
    const float* __restrict__ x, const float* __restrict__ w,
    const float* __restrict__ b, __half* __restrict__ outh,
    __half* __restrict__ outl)
{
    const int row = blockIdx.x;
    const int tid = threadIdx.x;
    const float4* xr = (const float4*)(x + (size_t)row * CC);
    float4 v = xr[tid];
    float s  = v.x + v.y + v.z + v.w;
    float ss = v.x*v.x + v.y*v.y + v.z*v.z + v.w*v.w;

    __shared__ float red0[8], red1[8];
    #pragma unroll
    for (int o = 16; o > 0; o >>= 1) {
        s  += __shfl_down_sync(0xffffffffu, s,  o);
        ss += __shfl_down_sync(0xffffffffu, ss, o);
    }
    const int wid = tid >> 5, lid = tid & 31;
    if (lid == 0) { red0[wid] = s; red1[wid] = ss; }
    __syncthreads();
    if (tid == 0) {
        float S = 0.f, SS = 0.f;
        #pragma unroll
        for (int i = 0; i < 8; i++) { S += red0[i]; SS += red1[i]; }
        float mu  = S * (1.f / CC);
        float var = SS * (1.f / CC) - mu * mu;
        red0[0] = mu;
        red1[0] = rsqrtf(var + EPS);
    }
    __syncthreads();
    const float mu = red0[0], rstd = red1[0];
    float4 wv = ((const float4*)w)[tid];
    float4 bv = ((const float4*)b)[tid];
    float ox = (v.x - mu) * rstd * wv.x + bv.x;
    float oy = (v.y - mu) * rstd * wv.y + bv.y;
    float oz = (v.z - mu) * rstd * wv.z + bv.z;
    float ow = (v.w - mu) * rstd * wv.w + bv.w;
    const size_t off = (size_t)row * CC + tid * 4;
    split_store2(outh, outl, off,     ox, oy);
    split_store2(outh, outl, off + 2, oz, ow);
}

// --------------------- fp16x2 cp.async pipelined GEMM -----------------------
// C[M,N] = epilogue(A[M,K] @ BT[N,K]^T + bias, res)
// EPI 0: C=+bias(fp32)        EPI 1: C=+bias+res(fp32)
// EPI 2: Ch/Cl=split(gelu(+bias))   EPI 3: Ch/Cl=split(+bias)
// CTA 128x128x32, 256 thr, warps 4(m) x 2(n); 3-stage cp.async, 2 CTAs/SM.

#define PITCH      80
#define TILE_B     (128 * PITCH)               // 10240
#define SOFF(st,w) (((st)*3 + (w)) * TILE_B)   // w: 0=Ah 1=Al 2=B
#define GEMM_SMEM  (9 * TILE_B)                // 92160

__device__ __forceinline__ void stage_load(
    uint32_t sb, int st,
    const __half* Ah, const __half* Al, const __half* Bh,
    int kb, int tid, int K)
{
    const int r  = tid >> 1;
    const int c0 = (tid & 1) * 2;
    const size_t gbase = (size_t)r * K + (size_t)kb * 32 + c0 * 8;
    const uint32_t sbase = sb + (uint32_t)(r * PITCH + c0 * 16);
    const __half* ptrs[3] = {Ah, Al, Bh};
    #pragma unroll
    for (int w = 0; w < 3; w++) {
        const __half* g = ptrs[w] + gbase;
        const uint32_t s = sbase + SOFF(st, w);
        CP16(s,      g);
        CP16(s + 16, g + 8);
    }
}

template<int EPI>
__global__ __launch_bounds__(256, 2) void gemm_f16_pipe(
    const __half* __restrict__ Ah, const __half* __restrict__ Al,
    const __half* __restrict__ Bh,
    const float* __restrict__ bias, const float* __restrict__ res,
    float* __restrict__ C, __half* __restrict__ Ch,
    __half* __restrict__ Cl, int M, int N, int K)
{
    extern __shared__ char smemc[];
    const uint32_t sb = smem_to_u32(smemc);

    const int tid    = threadIdx.x;
    const int wid    = tid >> 5, lane = tid & 31;
    const int warp_m = wid & 3;
    const int warp_n = wid >> 2;
    const int brow   = blockIdx.y * 128;
    const int bcol   = blockIdx.x * 128;

    const __half* Agh = Ah + (size_t)brow * K;
    const __half* Agl = Al + (size_t)brow * K;
    const __half* Bg  = Bh + (size_t)bcol * K;

    float acc[64];
    #pragma unroll
    for (int i = 0; i < 64; i++) acc[i] = 0.f;

    const int NKB = K >> 5;

    stage_load(sb, 0, Agh, Agl, Bg, 0, tid, K);
    CP_COMMIT();
    stage_load(sb, 1, Agh, Agl, Bg, 1, tid, K);
    CP_COMMIT();

    const int a_row = warp_m * 32 + (lane & 7) + ((lane >> 3) & 1) * 8;
    const uint32_t a_off = (uint32_t)(a_row * PITCH + (lane >> 4) * 16);
    const int b_row = warp_n * 64 + (lane & 7) + (lane >> 4) * 8;
    const uint32_t b_off = (uint32_t)(b_row * PITCH + ((lane >> 3) & 1) * 16);

    for (int kb = 0; kb < NKB; kb++) {
        CP_WAIT1();
        __syncthreads();

        if (kb + 2 < NKB) {
            stage_load(sb, (kb + 2) % 3, Agh, Agl, Bg, kb + 2, tid, K);
        }
        CP_COMMIT();

        const int st = kb % 3;
        const uint32_t sAh = sb + SOFF(st,0);
        const uint32_t sAl = sb + SOFF(st,1);
        const uint32_t sB  = sb + SOFF(st,2);

        #pragma unroll
        for (int k16 = 0; k16 < 2; k16++) {
            uint32_t ah[2][4], al[2][4];
            #pragma unroll
            for (int mt = 0; mt < 2; mt++) {
                const uint32_t off = a_off + mt * 16 * PITCH + k16 * 32;
                ldsm_x4(ah[mt], sAh + off);
                ldsm_x4(al[mt], sAl + off);
            }
            #pragma unroll
            for (int nt = 0; nt < 4; nt++) {
                uint32_t bh[4];
                ldsm_x4(bh, sB + b_off + nt * 16 * PITCH + k16 * 32);
                #pragma unroll
                for (int mt = 0; mt < 2; mt++)
                    #pragma unroll
                    for (int t = 0; t < 2; t++)
                        mma_f16(&acc[(mt*8 + nt*2 + t)*4], ah[mt], &bh[t*2]);
                #pragma unroll
                for (int mt = 0; mt < 2; mt++)
                    #pragma unroll
                    for (int t = 0; t < 2; t++)
                        mma_f16(&acc[(mt*8 + nt*2 + t)*4], al[mt], &bh[t*2]);
            }
        }
    }

    __syncthreads();

    // ---------------- epilogue ----------------
    const int erow = brow + warp_m * 32 + (lane >> 2);
    const int ecol = bcol + warp_n * 64 + (lane & 3) * 2;
    #pragma unroll
    for (int mt = 0; mt < 2; mt++) {
        #pragma unroll
        for (int j = 0; j < 8; j++) {
            const float* c = &acc[(mt*8 + j)*4];
            const int grow = erow + mt * 16;
            const int gcol = ecol + j * 8;
            float2 bvv = *(const float2*)(bias + gcol);
            float o0x = c[0] + bvv.x, o0y = c[1] + bvv.y;
            float o1x = c[2] + bvv.x, o1y = c[3] + bvv.y;
            if (EPI == 1) {
                float2 r0v = *(const float2*)(res + (size_t)grow * N + gcol);
                float2 r1v = *(const float2*)(res + (size_t)(grow+8) * N + gcol);
                o0x += r0v.x; o0y += r0v.y;
                o1x += r1v.x; o1y += r1v.y;
            }
            if (EPI == 2) {
                o0x = gelu_exact(o0x); o0y = gelu_exact(o0y);
                o1x = gelu_exact(o1x); o1y = gelu_exact(o1y);
            }
            if (EPI == 2 || EPI == 3) {
                split_store2(Ch, Cl, (size_t)grow * N + gcol,     o0x, o0y);
                split_store2(Ch, Cl, (size_t)(grow+8) * N + gcol, o1x, o1y);
            } else {
                *(float2*)(C + (size_t)grow * N + gcol)     = make_float2(o0x, o0y);
                *(float2*)(C + (size_t)(grow+8) * N + gcol) = make_float2(o1x, o1y);
            }
        }
    }
}

// --------------------- tensor-core flash attention --------------------------
// Block = 64 q-rows of one (b,h); 4 warps x m16. K-tiles of 32 keys,
// double-buffered cp.async. S = Qh*Kh + Ql*Kh + Qh*Kl (3 HMMA terms),
// online softmax in C-fragments, P repacked to A-frags, O += P*(Vh+Vl)
// via ldmatrix.trans on V. Writes ctx fp16 hi/lo.

#define FPITCH     144
#define FQ_BYTES   (64 * FPITCH)        // 9216
#define FKT_BYTES  (32 * FPITCH)        // 4608 per K/V tile
#define FSTG_BYTES (4 * FKT_BYTES)      // 18432: Kh,Kl,Vh,Vl
#define FSMEM      (2 * FQ_BYTES + 2 * FSTG_BYTES)   // 55296

__device__ __forceinline__ void flash_stage_load(
    uint32_t base, const __half* __restrict__ QKVh,
    const __half* __restrict__ QKVl, size_t rowbase, int hc, int kt, int tid)
{
    #pragma unroll
    for (int i = 0; i < 8; i++) {
        const int c   = tid + i * 128;   // 0..1023
        const int buf = c >> 8;          // 0 Kh, 1 Kl, 2 Vh, 3 Vl
        const int cc  = c & 255;
        const int row = cc >> 3, c16 = cc & 7;
        const __half* src = (buf & 1) ? QKVl : QKVh;
        const int colg = ((buf & 2) ? 2048 : 1024) + hc + c16 * 8;
        CP16(base + buf * FKT_BYTES + row * FPITCH + c16 * 16,
             src + (rowbase + (size_t)kt * 32 + row) * QKVN + colg);
    }
}

__global__ __launch_bounds__(128, 4) void flash_mma_kernel(
    const __half* __restrict__ QKVh, const __half* __restrict__ QKVl,
    __half* __restrict__ Oh, __half* __restrict__ Ol)
{
    extern __shared__ char fsm[];
    const uint32_t sb = smem_to_u32(fsm);
    const int tid = threadIdx.x, wid = tid >> 5, lane = tid & 31;
    const int qt = blockIdx.x, bh = blockIdx.y;
    const int b  = bh >> 4, hh = bh & 15;
    const size_t rowbase = (size_t)b * TT;
    const int hc = hh * 64;

    const uint32_t sQh = sb;
    const uint32_t sQl = sb + FQ_BYTES;
    const uint32_t stg0 = sb + 2 * FQ_BYTES;

    // ---- prologue: Q + stage0 (group 0), stage1 (group 1) ----
    {
        const int qrow0 = qt * 64;
        #pragma unroll
        for (int i = 0; i < 8; i++) {
            const int c = tid + i * 128;          // 0..1023
            const __half* src = (c < 512) ? QKVh : QKVl;
            const uint32_t dstb = (c < 512) ? sQh : sQl;
            const int cc = c & 511;
            const int row = cc >> 3, c16 = cc & 7;
            CP16(dstb + row * FPITCH + c16 * 16,
                 src + (rowbase + qrow0 + row) * QKVN + hc + c16 * 8);
        }
        flash_stage_load(stg0, QKVh, QKVl, rowbase, hc, 0, tid);
    }
    CP_COMMIT();
    const int nkt = 2 * qt + 2;
    flash_stage_load(stg0 + FSTG_BYTES, QKVh, QKVl, rowbase, hc, 1, tid);
    CP_COMMIT();

    // fragment offsets
    const int arow = (lane & 7) + ((lane >> 3) & 1) * 8;      // A rows
    const uint32_t a_off = (uint32_t)((wid * 16 + arow) * FPITCH + (lane >> 4) * 16);
    const int brow = (lane & 7) + (lane >> 4) * 8;            // B rows (non-trans)
    const uint32_t bsel = ((lane >> 3) & 1) * 16;
    // V trans: row = key, col-chunk = d
    const int vrow = (lane & 7) + ((lane >> 3) & 1) * 8;
    const uint32_t vsel = (lane >> 4) * 16;

    float o[32];
    #pragma unroll
    for (int i = 0; i < 32; i++) o[i] = 0.f;
    float m0 = -INFINITY, m1 = -INFINITY, l0 = 0.f, l1 = 0.f;
    uint32_t qh[4][4], ql[4][4];

    const int r0g = qt * 64 + wid * 16 + (lane >> 2);   // global row of c0/c1
    const int r1g = r0g + 8;                            // global row of c2/c3

    for (int kt = 0; kt < nkt; kt++) {
        CP_WAIT1();
        __syncthreads();

        if (kt == 0) {
            #pragma unroll
            for (int kc = 0; kc < 4; kc++) {
                ldsm_x4(qh[kc], sQh + a_off + kc * 32);
                ldsm_x4(ql[kc], sQl + a_off + kc * 32);
            }
        }

        const uint32_t bs  = stg0 + (kt & 1) * FSTG_BYTES;
        const uint32_t sKh = bs;
        const uint32_t sKl = bs + FKT_BYTES;
        const uint32_t sVh = bs + 2 * FKT_BYTES;
        const uint32_t sVl = bs + 3 * FKT_BYTES;

        // ---- S = Q K^T (3 emulation terms) ----
        float sc[4][4];
        #pragma unroll
        for (int t = 0; t < 4; t++)
            #pragma unroll
            for (int i = 0; i < 4; i++) sc[t][i] = 0.f;

        #pragma unroll
        for (int kc = 0; kc < 4; kc++) {
            #pragma unroll
            for (int ng = 0; ng < 2; ng++) {
                uint32_t kh4[4], kl4[4];
                const uint32_t off = (uint32_t)((ng * 16 + brow) * FPITCH) + bsel + kc * 32;
                ldsm_x4(kh4, sKh + off);
                ldsm_x4(kl4, sKl + off);
                mma_f16(sc[2*ng],   qh[kc], kh4);
                mma_f16(sc[2*ng+1], qh[kc], kh4 + 2);
                mma_f16(sc[2*ng],   ql[kc], kh4);
                mma_f16(sc[2*ng+1], ql[kc], kh4 + 2);
                mma_f16(sc[2*ng],   qh[kc], kl4);
                mma_f16(sc[2*ng+1], qh[kc], kl4 + 2);
            }
        }

        // scale + causal mask
        #pragma unroll
        for (int t = 0; t < 4; t++)
            #pragma unroll
            for (int i = 0; i < 4; i++) sc[t][i] *= 0.125f;
        if (kt * 32 + 31 > r0g) {
            #pragma unroll
            for (int t = 0; t < 4; t++) {
                const int colg = kt * 32 + t * 8 + (lane & 3) * 2;
                if (colg     > r0g) sc[t][0] = -INFINITY;
                if (colg + 1 > r0g) sc[t][1] = -INFINITY;
                if (colg     > r1g) sc[t][2] = -INFINITY;
                if (colg + 1 > r1g) sc[t][3] = -INFINITY;
            }
        }

        // ---- online softmax ----
        float t0 = -INFINITY, t1 = -INFINITY;
        #pragma unroll
        for (int t = 0; t < 4; t++) {
            t0 = fmaxf(t0, fmaxf(sc[t][0], sc[t][1]));
            t1 = fmaxf(t1, fmaxf(sc[t][2], sc[t][3]));
        }
        t0 = fmaxf(t0, __shfl_xor_sync(0xffffffffu, t0, 1));
        t0 = fmaxf(t0, __shfl_xor_sync(0xffffffffu, t0, 2));
        t1 = fmaxf(t1, __shfl_xor_sync(0xffffffffu, t1, 1));
        t1 = fmaxf(t1, __shfl_xor_sync(0xffffffffu, t1, 2));
        const float mn0 = fmaxf(m0, t0), mn1 = fmaxf(m1, t1);
        const float al0 = __expf(m0 - mn0), al1 = __expf(m1 - mn1);
        m0 = mn0; m1 = mn1;

        float ps0 = 0.f, ps1 = 0.f;
        #pragma unroll
        for (int t = 0; t < 4; t++) {
            sc[t][0] = __expf(sc[t][0] - mn0);
            sc[t][1] = __expf(sc[t][1] - mn0);
            sc[t][2] = __expf(sc[t][2] - mn1);
            sc[t][3] = __expf(sc[t][3] - mn1);
            ps0 += sc[t][0] + sc[t][1];
            ps1 += sc[t][2] + sc[t][3];
        }
        ps0 += __shfl_xor_sync(0xffffffffu, ps0, 1);
        ps0 += __shfl_xor_sync(0xffffffffu, ps0, 2);
        ps1 += __shfl_xor_sync(0xffffffffu, ps1, 1);
        ps1 += __shfl_xor_sync(0xffffffffu, ps1, 2);
        l0 = l0 * al0 + ps0;
        l1 = l1 * al1 + ps1;

        #pragma unroll
        for (int nt = 0; nt < 8; nt++) {
            o[nt*4 + 0] *= al0; o[nt*4 + 1] *= al0;
            o[nt*4 + 2] *= al1; o[nt*4 + 3] *= al1;
        }

        // pack P: C-frags -> A-frags (m16 x k32 = 2 k16 chunks)
        uint32_t pk[2][4];
        #pragma unroll
        for (int j = 0; j < 2; j++) {
            pk[j][0] = h2pack(sc[2*j][0],   sc[2*j][1]);
            pk[j][1] = h2pack(sc[2*j][2],   sc[2*j][3]);
            pk[j][2] = h2pack(sc[2*j+1][0], sc[2*j+1][1]);
            pk[j][3] = h2pack(sc[2*j+1][2], sc[2*j+1][3]);
        }

        // ---- O += P V (Vh + Vl terms, ldmatrix.trans) ----
        #pragma unroll
        for (int kc = 0; kc < 2; kc++) {
            #pragma unroll
            for (int ng = 0; ng < 4; ng++) {
                uint32_t vh4[4], vl4[4];
                const uint32_t voff =
                    (uint32_t)((kc * 16 + vrow) * FPITCH) + ng * 32 + vsel;
                ldsm_x4_t(vh4, sVh + voff);
                ldsm_x4_t(vl4, sVl + voff);
                mma_f16(&o[(2*ng)*4],   pk[kc], vh4);
                mma_f16(&o[(2*ng+1)*4], pk[kc], vh4 + 2);
                mma_f16(&o[(2*ng)*4],   pk[kc], vl4);
                mma_f16(&o[(2*ng+1)*4], pk[kc], vl4 + 2);
            }
        }

        __syncthreads();
        if (kt + 2 < nkt)
            flash_stage_load(stg0 + (kt & 1) * FSTG_BYTES,
                             QKVh, QKVl, rowbase, hc, kt + 2, tid);
        CP_COMMIT();
    }

    // ---- write ctx (fp16 hi/lo) ----
    const float inv0 = 1.f / l0, inv1 = 1.f / l1;
    const size_t tok0 = rowbase + qt * 64 + wid * 16 + (lane >> 2);
    #pragma unroll
    for (int nt = 0; nt < 8; nt++) {
        const int col = hc + nt * 8 + (lane & 3) * 2;
        split_store2(Oh, Ol, tok0 * CC + col,
                     o[nt*4 + 0] * inv0, o[nt*4 + 1] * inv0);
        split_store2(Oh, Ol, (tok0 + 8) * CC + col,
                     o[nt*4 + 2] * inv1, o[nt*4 + 3] * inv1);
    }
}

// ------------------------------ launch --------------------------------------
extern "C" void kernel_launch(void* const* d_in, const int* in_sizes, int n_in,
                              void* d_out, int out_size)
{
    (void)in_sizes; (void)n_in; (void)out_size;
    const float* x    = (const float*)d_in[0];
    const float* ln1w = (const float*)d_in[2];
    const float* ln1b = (const float*)d_in[3];
    const float* ln2w = (const float*)d_in[4];
    const float* ln2b = (const float*)d_in[5];
    const float* wq   = (const float*)d_in[6];
    const float* bq   = (const float*)d_in[7];
    const float* wk   = (const float*)d_in[8];
    const float* bk   = (const float*)d_in[9];
    const float* wv   = (const float*)d_in[10];
    const float* bv   = (const float*)d_in[11];
    const float* wo   = (const float*)d_in[12];
    const float* bo   = (const float*)d_in[13];
    const float* w1   = (const float*)d_in[14];
    const float* b1   = (const float*)d_in[15];
    const float* w2   = (const float*)d_in[16];
    const float* b2   = (const float*)d_in[17];
    float* out = (float*)d_out;

    __half *hh, *hl, *ctxh, *ctxl, *ffh, *ffl, *qkvh, *qkvl;
    __half *wqkvT, *woT, *w1T, *w2T;
    float *x2, *bqkv;
    cudaGetSymbolAddress((void**)&hh,   g_hh);
    cudaGetSymbolAddress((void**)&hl,   g_hl);
    cudaGetSymbolAddress((void**)&ctxh, g_ctxh);
    cudaGetSymbolAddress((void**)&ctxl, g_ctxl);
    cudaGetSymbolAddress((void**)&ffh,  g_ffh);
    cudaGetSymbolAddress((void**)&ffl,  g_ffl);
    cudaGetSymbolAddress((void**)&qkvh, g_qkvh);
    cudaGetSymbolAddress((void**)&qkvl, g_qkvl);
    cudaGetSymbolAddress((void**)&x2,   g_x2);
    cudaGetSymbolAddress((void**)&bqkv, g_bqkv);
    cudaGetSymbolAddress((void**)&wqkvT, g_wqkvT);
    cudaGetSymbolAddress((void**)&woT, g_woT);
    cudaGetSymbolAddress((void**)&w1T, g_w1T);
    cudaGetSymbolAddress((void**)&w2T, g_w2T);

    cudaFuncSetAttribute(gemm_f16_pipe<0>, cudaFuncAttributeMaxDynamicSharedMemorySize, GEMM_SMEM);
    cudaFuncSetAttribute(gemm_f16_pipe<1>, cudaFuncAttributeMaxDynamicSharedMemorySize, GEMM_SMEM);
    cudaFuncSetAttribute(gemm_f16_pipe<2>, cudaFuncAttributeMaxDynamicSharedMemorySize, GEMM_SMEM);
    cudaFuncSetAttribute(gemm_f16_pipe<3>, cudaFuncAttributeMaxDynamicSharedMemorySize, GEMM_SMEM);
    cudaFuncSetAttribute(flash_mma_kernel,  cudaFuncAttributeMaxDynamicSharedMemorySize, FSMEM);

    const dim3 tB(32, 8);
    transpose_h_kernel<<<dim3(CC/32,  CC/32),  tB>>>(wq, wqkvT,           CC,  CC);
    transpose_h_kernel<<<dim3(CC/32,  CC/32),  tB>>>(wk, wqkvT + 1024*CC, CC,  CC);
    transpose_h_kernel<<<dim3(CC/32,  CC/32),  tB>>>(wv, wqkvT + 2048*CC, CC,  CC);
    transpose_h_kernel<<<dim3(CC/32,  CC/32),  tB>>>(wo, woT, CC,  CC);
    transpose_h_kernel<<<dim3(FFN/32, CC/32),  tB>>>(w1, w1T, CC,  FFN);
    transpose_h_kernel<<<dim3(CC/32,  FFN/32), tB>>>(w2, w2T, FFN, CC);
    bias_concat_kernel<<<12, 256>>>(bq, bk, bv, bqkv);

    const dim3 gQKV(QKVN / 128, NROWS / 128);
    const dim3 gC  (CC   / 128, NROWS / 128);
    const dim3 gF  (FFN  / 128, NROWS / 128);

    // 1. h = LN1(x)
    ln_split_kernel<<<NROWS, 256>>>(x, ln1w, ln1b, hh, hl);
    // 2. qkv = h@Wqkv + bqkv  (fp16 hi/lo out)
    gemm_f16_pipe<3><<<gQKV, 256, GEMM_SMEM>>>(hh, hl, wqkvT, bqkv,
                                               nullptr, nullptr, qkvh, qkvl,
                                               NROWS, QKVN, CC);
    // 3. ctx = causal-softmax(qk^T/8) v  (tensor-core flash)
    flash_mma_kernel<<<dim3(TT / 64, BB * HHD), 128, FSMEM>>>(qkvh, qkvl,
                                                              ctxh, ctxl);
    // 4. x2 = x + ctx@wo + bo
    gemm_f16_pipe<1><<<gC, 256, GEMM_SMEM>>>(ctxh, ctxl, woT, bo, x,
                                             x2, nullptr, nullptr,
                                             NROWS, CC, CC);
    // 5. h = LN2(x2)
    ln_split_kernel<<<NROWS, 256>>>(x2, ln2w, ln2b, hh, hl);
    // 6. ff = gelu(h@w1 + b1)  (fp16 hi/lo out)
    gemm_f16_pipe<2><<<gF, 256, GEMM_SMEM>>>(hh, hl, w1T, b1, nullptr,
                                             nullptr, ffh, ffl,
                                             NROWS, FFN, CC);
    // 7. out = x2 + ff@w2 + b2
    gemm_f16_pipe<1><<<gC, 256, GEMM_SMEM>>>(ffh, ffl, w2T, b2, x2,
                                             out, nullptr, nullptr,
                                             NROWS, CC, FFN);
}

// round 15
// speedup vs baseline: 3.4542x; 1.5329x over previous
#include <cuda_runtime.h>
#include <cuda_fp16.h>
#include <math.h>
#include <stdint.h>

// Problem constants
#define BB   8
#define TT   1024
#define CC   1024
#define HHD  16
#define DD   64
#define NROWS (BB*TT)      // 8192
#define FFN   (4*CC)       // 4096
#define QKVN 3072
#define EPS  1e-5f

// -------------------- scratch (static device memory; no allocs) ------------
// fp16 activations
__device__ __half g_h  [(size_t)NROWS*CC];
__device__ __half g_ctx[(size_t)NROWS*CC];
__device__ __half g_ff [(size_t)NROWS*FFN];
// qkv kept hi/lo (attention precision)
__device__ __half g_qkvh[(size_t)NROWS*QKVN];
__device__ __half g_qkvl[(size_t)NROWS*QKVN];
// fp32 buffers
__device__ float g_x2 [(size_t)NROWS*CC];
// fp16 transposed weights [N][K] K-major
__device__ __half g_wqkvT[(size_t)QKVN*CC];
__device__ __half g_woT[(size_t)CC*CC];
__device__ __half g_w1T[(size_t)FFN*CC];
__device__ __half g_w2T[(size_t)CC*FFN];
__device__ float g_bqkv[QKVN];

// ---------------------------- helpers ---------------------------------------
__device__ __forceinline__ uint32_t smem_to_u32(const void* p) {
    uint32_t a;
    asm("{ .reg .u64 t; cvta.to.shared.u64 t, %1; cvt.u32.u64 %0, t; }"
        : "=r"(a) : "l"(p));
    return a;
}
__device__ __forceinline__ void ldsm_x4(uint32_t* r, uint32_t addr) {
    asm volatile("ldmatrix.sync.aligned.m8n8.x4.shared.b16 {%0,%1,%2,%3}, [%4];"
                 : "=r"(r[0]), "=r"(r[1]), "=r"(r[2]), "=r"(r[3]) : "r"(addr));
}
__device__ __forceinline__ void ldsm_x4_t(uint32_t* r, uint32_t addr) {
    asm volatile("ldmatrix.sync.aligned.m8n8.x4.trans.shared.b16 {%0,%1,%2,%3}, [%4];"
                 : "=r"(r[0]), "=r"(r[1]), "=r"(r[2]), "=r"(r[3]) : "r"(addr));
}
__device__ __forceinline__ void mma_f16(float* c, const uint32_t* a,
                                        const uint32_t* b) {
    asm volatile(
        "mma.sync.aligned.m16n8k16.row.col.f32.f16.f16.f32 "
        "{%0,%1,%2,%3}, {%4,%5,%6,%7}, {%8,%9}, {%0,%1,%2,%3};"
        : "+f"(c[0]), "+f"(c[1]), "+f"(c[2]), "+f"(c[3])
        : "r"(a[0]), "r"(a[1]), "r"(a[2]), "r"(a[3]), "r"(b[0]), "r"(b[1]));
}
#define CP16(sa, gp) \
    asm volatile("cp.async.cg.shared.global [%0], [%1], 16;" \
                 :: "r"(sa), "l"(gp) : "memory")
#define CP_COMMIT() asm volatile("cp.async.commit_group;" ::: "memory")
#define CP_WAIT1()  asm volatile("cp.async.wait_group 1;" ::: "memory")

__device__ __forceinline__ float gelu_exact(float v) {
    return 0.5f * v * (1.0f + erff(v * 0.70710678118654752f));
}
__device__ __forceinline__ void split_store2(__half* Ch, __half* Cl,
                                             size_t off, float x, float y) {
    __half2 h, l;
    h.x = __float2half_rn(x); h.y = __float2half_rn(y);
    l.x = __float2half_rn(x - __half2float(h.x));
    l.y = __float2half_rn(y - __half2float(h.y));
    *(__half2*)(Ch + off) = h;
    *(__half2*)(Cl + off) = l;
}
__device__ __forceinline__ uint32_t h2pack(float x, float y) {
    __half2 h = __floats2half2_rn(x, y);
    return *(uint32_t*)&h;
}

// --------------------------- weight transpose (fp16) ------------------------
__global__ __launch_bounds__(256) void transpose_h_kernel(
    const float* __restrict__ W, __half* __restrict__ WT, int K, int N)
{
    __shared__ float t[32][33];
    const int n0 = blockIdx.x * 32, k0 = blockIdx.y * 32;
    const int tx = threadIdx.x, ty = threadIdx.y;
    #pragma unroll
    for (int i = 0; i < 32; i += 8)
        t[ty + i][tx] = W[(size_t)(k0 + ty + i) * N + n0 + tx];
    __syncthreads();
    #pragma unroll
    for (int i = 0; i < 32; i += 8)
        WT[(size_t)(n0 + ty + i) * K + k0 + tx] = __float2half_rn(t[tx][ty + i]);
}

__global__ void bias_concat_kernel(const float* bq, const float* bk,
                                   const float* bv, float* out)
{
    int i = blockIdx.x * blockDim.x + threadIdx.x;
    if (i < 1024)       out[i] = bq[i];
    else if (i < 2048)  out[i] = bk[i - 1024];
    else if (i < 3072)  out[i] = bv[i - 2048];
}

// ---------------------------- LayerNorm (fp16 out) --------------------------
__global__ __launch_bounds__(256) void ln_h_kernel(
    const float* __restrict__ x, const float* __restrict__ w,
    const float* __restrict__ b, __half* __restrict__ outh)
{
    const int row = blockIdx.x;
    const int tid = threadIdx.x;
    const float4* xr = (const float4*)(x + (size_t)row * CC);
    float4 v = xr[tid];
    float s  = v.x + v.y + v.z + v.w;
    float ss = v.x*v.x + v.y*v.y + v.z*v.z + v.w*v.w;

    __shared__ float red0[8], red1[8];
    #pragma unroll
    for (int o = 16; o > 0; o >>= 1) {
        s  += __shfl_down_sync(0xffffffffu, s,  o);
        ss += __shfl_down_sync(0xffffffffu, ss, o);
    }
    const int wid = tid >> 5, lid = tid & 31;
    if (lid == 0) { red0[wid] = s; red1[wid] = ss; }
    __syncthreads();
    if (tid == 0) {
        float S = 0.f, SS = 0.f;
        #pragma unroll
        for (int i = 0; i < 8; i++) { S += red0[i]; SS += red1[i]; }
        float mu  = S * (1.f / CC);
        float var = SS * (1.f / CC) - mu * mu;
        red0[0] = mu;
        red1[0] = rsqrtf(var + EPS);
    }
    __syncthreads();
    const float mu = red0[0], rstd = red1[0];
    float4 wv = ((const float4*)w)[tid];
    float4 bv = ((const float4*)b)[tid];
    float ox = (v.x - mu) * rstd * wv.x + bv.x;
    float oy = (v.y - mu) * rstd * wv.y + bv.y;
    float oz = (v.z - mu) * rstd * wv.z + bv.z;
    float ow = (v.w - mu) * rstd * wv.w + bv.w;
    const size_t off = (size_t)row * CC + tid * 4;
    *(__half2*)(g_h ? (outh + off)     : nullptr) = __floats2half2_rn(ox, oy);
    *(__half2*)(outh + off + 2) = __floats2half2_rn(oz, ow);
}

// --------------------- fp16 cp.async pipelined GEMM -------------------------
// C[M,N] = epilogue(A[M,K] @ BT[N,K]^T + bias, res); A,B single fp16.
// EPI 0: C=+bias(fp32)        EPI 1: C=+bias+res(fp32)
// EPI 2: Ch=fp16(gelu(+bias)) EPI 3: Ch/Cl=split(+bias)
// CTA 128x128x32, 256 thr, warps 4(m) x 2(n); 3-stage cp.async, 2 CTAs/SM.

#define PITCH      80
#define TILE_B     (128 * PITCH)               // 10240
#define SOFF(st,w) (((st)*2 + (w)) * TILE_B)   // w: 0=A 1=B
#define GEMM_SMEM  (6 * TILE_B)                // 61440

__device__ __forceinline__ void stage_load(
    uint32_t sb, int st, const __half* A, const __half* B,
    int kb, int tid, int K)
{
    const int r  = tid >> 1;
    const int c0 = (tid & 1) * 2;
    const size_t gbase = (size_t)r * K + (size_t)kb * 32 + c0 * 8;
    const uint32_t sbase = sb + (uint32_t)(r * PITCH + c0 * 16);
    {
        const __half* g = A + gbase;
        const uint32_t s = sbase + SOFF(st, 0);
        CP16(s,      g);
        CP16(s + 16, g + 8);
    }
    {
        const __half* g = B + gbase;
        const uint32_t s = sbase + SOFF(st, 1);
        CP16(s,      g);
        CP16(s + 16, g + 8);
    }
}

template<int EPI>
__global__ __launch_bounds__(256, 2) void gemm_f16_pipe(
    const __half* __restrict__ A, const __half* __restrict__ Bh,
    const float* __restrict__ bias, const float* __restrict__ res,
    float* __restrict__ C, __half* __restrict__ Ch,
    __half* __restrict__ Cl, int M, int N, int K)
{
    extern __shared__ char smemc[];
    const uint32_t sb = smem_to_u32(smemc);

    const int tid    = threadIdx.x;
    const int wid    = tid >> 5, lane = tid & 31;
    const int warp_m = wid & 3;
    const int warp_n = wid >> 2;
    const int brow   = blockIdx.y * 128;
    const int bcol   = blockIdx.x * 128;

    const __half* Ag = A  + (size_t)brow * K;
    const __half* Bg = Bh + (size_t)bcol * K;

    float acc[64];
    #pragma unroll
    for (int i = 0; i < 64; i++) acc[i] = 0.f;

    const int NKB = K >> 5;

    stage_load(sb, 0, Ag, Bg, 0, tid, K);
    CP_COMMIT();
    stage_load(sb, 1, Ag, Bg, 1, tid, K);
    CP_COMMIT();

    const int a_row = warp_m * 32 + (lane & 7) + ((lane >> 3) & 1) * 8;
    const uint32_t a_off = (uint32_t)(a_row * PITCH + (lane >> 4) * 16);
    const int b_row = warp_n * 64 + (lane & 7) + (lane >> 4) * 8;
    const uint32_t b_off = (uint32_t)(b_row * PITCH + ((lane >> 3) & 1) * 16);

    for (int kb = 0; kb < NKB; kb++) {
        CP_WAIT1();
        __syncthreads();

        if (kb + 2 < NKB) {
            stage_load(sb, (kb + 2) % 3, Ag, Bg, kb + 2, tid, K);
        }
        CP_COMMIT();

        const int st = kb % 3;
        const uint32_t sA = sb + SOFF(st,0);
        const uint32_t sB = sb + SOFF(st,1);

        #pragma unroll
        for (int k16 = 0; k16 < 2; k16++) {
            uint32_t ah[2][4];
            #pragma unroll
            for (int mt = 0; mt < 2; mt++)
                ldsm_x4(ah[mt], sA + a_off + mt * 16 * PITCH + k16 * 32);
            #pragma unroll
            for (int nt = 0; nt < 4; nt++) {
                uint32_t bh[4];
                ldsm_x4(bh, sB + b_off + nt * 16 * PITCH + k16 * 32);
                #pragma unroll
                for (int mt = 0; mt < 2; mt++)
                    #pragma unroll
                    for (int t = 0; t < 2; t++)
                        mma_f16(&acc[(mt*8 + nt*2 + t)*4], ah[mt], &bh[t*2]);
            }
        }
    }

    __syncthreads();

    // ---------------- epilogue ----------------
    const int erow = brow + warp_m * 32 + (lane >> 2);
    const int ecol = bcol + warp_n * 64 + (lane & 3) * 2;
    #pragma unroll
    for (int mt = 0; mt < 2; mt++) {
        #pragma unroll
        for (int j = 0; j < 8; j++) {
            const float* c = &acc[(mt*8 + j)*4];
            const int grow = erow + mt * 16;
            const int gcol = ecol + j * 8;
            float2 bvv = *(const float2*)(bias + gcol);
            float o0x = c[0] + bvv.x, o0y = c[1] + bvv.y;
            float o1x = c[2] + bvv.x, o1y = c[3] + bvv.y;
            if (EPI == 1) {
                float2 r0v = *(const float2*)(res + (size_t)grow * N + gcol);
                float2 r1v = *(const float2*)(res + (size_t)(grow+8) * N + gcol);
                o0x += r0v.x; o0y += r0v.y;
                o1x += r1v.x; o1y += r1v.y;
            }
            if (EPI == 2) {
                o0x = gelu_exact(o0x); o0y = gelu_exact(o0y);
                o1x = gelu_exact(o1x); o1y = gelu_exact(o1y);
                *(__half2*)(Ch + (size_t)grow * N + gcol)
                    = __floats2half2_rn(o0x, o0y);
                *(__half2*)(Ch + (size_t)(grow+8) * N + gcol)
                    = __floats2half2_rn(o1x, o1y);
            } else if (EPI == 3) {
                split_store2(Ch, Cl, (size_t)grow * N + gcol,     o0x, o0y);
                split_store2(Ch, Cl, (size_t)(grow+8) * N + gcol, o1x, o1y);
            } else {
                *(float2*)(C + (size_t)grow * N + gcol)     = make_float2(o0x, o0y);
                *(float2*)(C + (size_t)(grow+8) * N + gcol) = make_float2(o1x, o1y);
            }
        }
    }
}

// --------------------- tensor-core flash attention --------------------------
// Block = 64 q-rows of one (b,h); 4 warps x m16. K-tiles of 32 keys,
// double-buffered cp.async. S = Qh*Kh + Ql*Kh + Qh*Kl, online softmax,
// O += P*(Vh+Vl). Writes ctx single fp16.

#define FPITCH     144
#define FQ_BYTES   (64 * FPITCH)
#define FKT_BYTES  (32 * FPITCH)
#define FSTG_BYTES (4 * FKT_BYTES)
#define FSMEM      (2 * FQ_BYTES + 2 * FSTG_BYTES)   // 55296

__device__ __forceinline__ void flash_stage_load(
    uint32_t base, const __half* __restrict__ QKVh,
    const __half* __restrict__ QKVl, size_t rowbase, int hc, int kt, int tid)
{
    #pragma unroll
    for (int i = 0; i < 8; i++) {
        const int c   = tid + i * 128;
        const int buf = c >> 8;          // 0 Kh, 1 Kl, 2 Vh, 3 Vl
        const int cc  = c & 255;
        const int row = cc >> 3, c16 = cc & 7;
        const __half* src = (buf & 1) ? QKVl : QKVh;
        const int colg = ((buf & 2) ? 2048 : 1024) + hc + c16 * 8;
        CP16(base + buf * FKT_BYTES + row * FPITCH + c16 * 16,
             src + (rowbase + (size_t)kt * 32 + row) * QKVN + colg);
    }
}

__global__ __launch_bounds__(128, 4) void flash_mma_kernel(
    const __half* __restrict__ QKVh, const __half* __restrict__ QKVl,
    __half* __restrict__ O)
{
    extern __shared__ char fsm[];
    const uint32_t sb = smem_to_u32(fsm);
    const int tid = threadIdx.x, wid = tid >> 5, lane = tid & 31;
    const int qt = blockIdx.x, bh = blockIdx.y;
    const int b  = bh >> 4, hh = bh & 15;
    const size_t rowbase = (size_t)b * TT;
    const int hc = hh * 64;

    const uint32_t sQh = sb;
    const uint32_t sQl = sb + FQ_BYTES;
    const uint32_t stg0 = sb + 2 * FQ_BYTES;

    {
        const int qrow0 = qt * 64;
        #pragma unroll
        for (int i = 0; i < 8; i++) {
            const int c = tid + i * 128;
            const __half* src = (c < 512) ? QKVh : QKVl;
            const uint32_t dstb = (c < 512) ? sQh : sQl;
            const int cc = c & 511;
            const int row = cc >> 3, c16 = cc & 7;
            CP16(dstb + row * FPITCH + c16 * 16,
                 src + (rowbase + qrow0 + row) * QKVN + hc + c16 * 8);
        }
        flash_stage_load(stg0, QKVh, QKVl, rowbase, hc, 0, tid);
    }
    CP_COMMIT();
    const int nkt = 2 * qt + 2;
    flash_stage_load(stg0 + FSTG_BYTES, QKVh, QKVl, rowbase, hc, 1, tid);
    CP_COMMIT();

    const int arow = (lane & 7) + ((lane >> 3) & 1) * 8;
    const uint32_t a_off = (uint32_t)((wid * 16 + arow) * FPITCH + (lane >> 4) * 16);
    const int brow = (lane & 7) + (lane >> 4) * 8;
    const uint32_t bsel = ((lane >> 3) & 1) * 16;
    const int vrow = (lane & 7) + ((lane >> 3) & 1) * 8;
    const uint32_t vsel = (lane >> 4) * 16;

    float o[32];
    #pragma unroll
    for (int i = 0; i < 32; i++) o[i] = 0.f;
    float m0 = -INFINITY, m1 = -INFINITY, l0 = 0.f, l1 = 0.f;
    uint32_t qh[4][4], ql[4][4];

    const int r0g = qt * 64 + wid * 16 + (lane >> 2);
    const int r1g = r0g + 8;

    for (int kt = 0; kt < nkt; kt++) {
        CP_WAIT1();
        __syncthreads();

        if (kt == 0) {
            #pragma unroll
            for (int kc = 0; kc < 4; kc++) {
                ldsm_x4(qh[kc], sQh + a_off + kc * 32);
                ldsm_x4(ql[kc], sQl + a_off + kc * 32);
            }
        }

        const uint32_t bs  = stg0 + (kt & 1) * FSTG_BYTES;
        const uint32_t sKh = bs;
        const uint32_t sKl = bs + FKT_BYTES;
        const uint32_t sVh = bs + 2 * FKT_BYTES;
        const uint32_t sVl = bs + 3 * FKT_BYTES;

        float sc[4][4];
        #pragma unroll
        for (int t = 0; t < 4; t++)
            #pragma unroll
            for (int i = 0; i < 4; i++) sc[t][i] = 0.f;

        #pragma unroll
        for (int kc = 0; kc < 4; kc++) {
            #pragma unroll
            for (int ng = 0; ng < 2; ng++) {
                uint32_t kh4[4], kl4[4];
                const uint32_t off = (uint32_t)((ng * 16 + brow) * FPITCH) + bsel + kc * 32;
                ldsm_x4(kh4, sKh + off);
                ldsm_x4(kl4, sKl + off);
                mma_f16(sc[2*ng],   qh[kc], kh4);
                mma_f16(sc[2*ng+1], qh[kc], kh4 + 2);
                mma_f16(sc[2*ng],   ql[kc], kh4);
                mma_f16(sc[2*ng+1], ql[kc], kh4 + 2);
                mma_f16(sc[2*ng],   qh[kc], kl4);
                mma_f16(sc[2*ng+1], qh[kc], kl4 + 2);
            }
        }

        #pragma unroll
        for (int t = 0; t < 4; t++)
            #pragma unroll
            for (int i = 0; i < 4; i++) sc[t][i] *= 0.125f;
        if (kt * 32 + 31 > r0g) {
            #pragma unroll
            for (int t = 0; t < 4; t++) {
                const int colg = kt * 32 + t * 8 + (lane & 3) * 2;
                if (colg     > r0g) sc[t][0] = -INFINITY;
                if (colg + 1 > r0g) sc[t][1] = -INFINITY;
                if (colg     > r1g) sc[t][2] = -INFINITY;
                if (colg + 1 > r1g) sc[t][3] = -INFINITY;
            }
        }

        float t0 = -INFINITY, t1 = -INFINITY;
        #pragma unroll
        for (int t = 0; t < 4; t++) {
            t0 = fmaxf(t0, fmaxf(sc[t][0], sc[t][1]));
            t1 = fmaxf(t1, fmaxf(sc[t][2], sc[t][3]));
        }
        t0 = fmaxf(t0, __shfl_xor_sync(0xffffffffu, t0, 1));
        t0 = fmaxf(t0, __shfl_xor_sync(0xffffffffu, t0, 2));
        t1 = fmaxf(t1, __shfl_xor_sync(0xffffffffu, t1, 1));
        t1 = fmaxf(t1, __shfl_xor_sync(0xffffffffu, t1, 2));
        const float mn0 = fmaxf(m0, t0), mn1 = fmaxf(m1, t1);
        const float al0 = __expf(m0 - mn0), al1 = __expf(m1 - mn1);
        m0 = mn0; m1 = mn1;

        float ps0 = 0.f, ps1 = 0.f;
        #pragma unroll
        for (int t = 0; t < 4; t++) {
            sc[t][0] = __expf(sc[t][0] - mn0);
            sc[t][1] = __expf(sc[t][1] - mn0);
            sc[t][2] = __expf(sc[t][2] - mn1);
            sc[t][3] = __expf(sc[t][3] - mn1);
            ps0 += sc[t][0] + sc[t][1];
            ps1 += sc[t][2] + sc[t][3];
        }
        ps0 += __shfl_xor_sync(0xffffffffu, ps0, 1);
        ps0 += __shfl_xor_sync(0xffffffffu, ps0, 2);
        ps1 += __shfl_xor_sync(0xffffffffu, ps1, 1);
        ps1 += __shfl_xor_sync(0xffffffffu, ps1, 2);
        l0 = l0 * al0 + ps0;
        l1 = l1 * al1 + ps1;

        #pragma unroll
        for (int nt = 0; nt < 8; nt++) {
            o[nt*4 + 0] *= al0; o[nt*4 + 1] *= al0;
            o[nt*4 + 2] *= al1; o[nt*4 + 3] *= al1;
        }

        uint32_t pk[2][4];
        #pragma unroll
        for (int j = 0; j < 2; j++) {
            pk[j][0] = h2pack(sc[2*j][0],   sc[2*j][1]);
            pk[j][1] = h2pack(sc[2*j][2],   sc[2*j][3]);
            pk[j][2] = h2pack(sc[2*j+1][0], sc[2*j+1][1]);
            pk[j][3] = h2pack(sc[2*j+1][2], sc[2*j+1][3]);
        }

        #pragma unroll
        for (int kc = 0; kc < 2; kc++) {
            #pragma unroll
            for (int ng = 0; ng < 4; ng++) {
                uint32_t vh4[4], vl4[4];
                const uint32_t voff =
                    (uint32_t)((kc * 16 + vrow) * FPITCH) + ng * 32 + vsel;
                ldsm_x4_t(vh4, sVh + voff);
                ldsm_x4_t(vl4, sVl + voff);
                mma_f16(&o[(2*ng)*4],   pk[kc], vh4);
                mma_f16(&o[(2*ng+1)*4], pk[kc], vh4 + 2);
                mma_f16(&o[(2*ng)*4],   pk[kc], vl4);
                mma_f16(&o[(2*ng+1)*4], pk[kc], vl4 + 2);
            }
        }

        __syncthreads();
        if (kt + 2 < nkt)
            flash_stage_load(stg0 + (kt & 1) * FSTG_BYTES,
                             QKVh, QKVl, rowbase, hc, kt + 2, tid);
        CP_COMMIT();
    }

    // ---- write ctx (single fp16) ----
    const float inv0 = 1.f / l0, inv1 = 1.f / l1;
    const size_t tok0 = rowbase + qt * 64 + wid * 16 + (lane >> 2);
    #pragma unroll
    for (int nt = 0; nt < 8; nt++) {
        const int col = hc + nt * 8 + (lane & 3) * 2;
        *(__half2*)(O + tok0 * CC + col)
            = __floats2half2_rn(o[nt*4 + 0] * inv0, o[nt*4 + 1] * inv0);
        *(__half2*)(O + (tok0 + 8) * CC + col)
            = __floats2half2_rn(o[nt*4 + 2] * inv1, o[nt*4 + 3] * inv1);
    }
}

// ------------------------------ launch --------------------------------------
extern "C" void kernel_launch(void* const* d_in, const int* in_sizes, int n_in,
                              void* d_out, int out_size)
{
    (void)in_sizes; (void)n_in; (void)out_size;
    const float* x    = (const float*)d_in[0];
    const float* ln1w = (const float*)d_in[2];
    const float* ln1b = (const float*)d_in[3];
    const float* ln2w = (const float*)d_in[4];
    const float* ln2b = (const float*)d_in[5];
    const float* wq   = (const float*)d_in[6];
    const float* bq   = (const float*)d_in[7];
    const float* wk   = (const float*)d_in[8];
    const float* bk   = (const float*)d_in[9];
    const float* wv   = (const float*)d_in[10];
    const float* bv   = (const float*)d_in[11];
    const float* wo   = (const float*)d_in[12];
    const float* bo   = (const float*)d_in[13];
    const float* w1   = (const float*)d_in[14];
    const float* b1   = (const float*)d_in[15];
    const float* w2   = (const float*)d_in[16];
    const float* b2   = (const float*)d_in[17];
    float* out = (float*)d_out;

    __half *h, *ctx, *ff, *qkvh, *qkvl;
    __half *wqkvT, *woT, *w1T, *w2T;
    float *x2, *bqkv;
    cudaGetSymbolAddress((void**)&h,    g_h);
    cudaGetSymbolAddress((void**)&ctx,  g_ctx);
    cudaGetSymbolAddress((void**)&ff,   g_ff);
    cudaGetSymbolAddress((void**)&qkvh, g_qkvh);
    cudaGetSymbolAddress((void**)&qkvl, g_qkvl);
    cudaGetSymbolAddress((void**)&x2,   g_x2);
    cudaGetSymbolAddress((void**)&bqkv, g_bqkv);
    cudaGetSymbolAddress((void**)&wqkvT, g_wqkvT);
    cudaGetSymbolAddress((void**)&woT, g_woT);
    cudaGetSymbolAddress((void**)&w1T, g_w1T);
    cudaGetSymbolAddress((void**)&w2T, g_w2T);

    cudaFuncSetAttribute(gemm_f16_pipe<0>, cudaFuncAttributeMaxDynamicSharedMemorySize, GEMM_SMEM);
    cudaFuncSetAttribute(gemm_f16_pipe<1>, cudaFuncAttributeMaxDynamicSharedMemorySize, GEMM_SMEM);
    cudaFuncSetAttribute(gemm_f16_pipe<2>, cudaFuncAttributeMaxDynamicSharedMemorySize, GEMM_SMEM);
    cudaFuncSetAttribute(gemm_f16_pipe<3>, cudaFuncAttributeMaxDynamicSharedMemorySize, GEMM_SMEM);
    cudaFuncSetAttribute(flash_mma_kernel,  cudaFuncAttributeMaxDynamicSharedMemorySize, FSMEM);

    const dim3 tB(32, 8);
    transpose_h_kernel<<<dim3(CC/32,  CC/32),  tB>>>(wq, wqkvT,           CC,  CC);
    transpose_h_kernel<<<dim3(CC/32,  CC/32),  tB>>>(wk, wqkvT + 1024*CC, CC,  CC);
    transpose_h_kernel<<<dim3(CC/32,  CC/32),  tB>>>(wv, wqkvT + 2048*CC, CC,  CC);
    transpose_h_kernel<<<dim3(CC/32,  CC/32),  tB>>>(wo, woT, CC,  CC);
    transpose_h_kernel<<<dim3(FFN/32, CC/32),  tB>>>(w1, w1T, CC,  FFN);
    transpose_h_kernel<<<dim3(CC/32,  FFN/32), tB>>>(w2, w2T, FFN, CC);
    bias_concat_kernel<<<12, 256>>>(bq, bk, bv, bqkv);

    const dim3 gQKV(QKVN / 128, NROWS / 128);
    const dim3 gC  (CC   / 128, NROWS / 128);
    const dim3 gF  (FFN  / 128, NROWS / 128);

    // 1. h = LN1(x)  (fp16)
    ln_h_kernel<<<NROWS, 256>>>(x, ln1w, ln1b, h);
    // 2. qkv = h@Wqkv + bqkv  (hi/lo fp16 out: keeps attention precision)
    gemm_f16_pipe<3><<<gQKV, 256, GEMM_SMEM>>>(h, wqkvT, bqkv,
                                               nullptr, nullptr, qkvh, qkvl,
                                               NROWS, QKVN, CC);
    // 3. ctx = causal-softmax(qk^T/8) v  (tensor-core flash, fp16 out)
    flash_mma_kernel<<<dim3(TT / 64, BB * HHD), 128, FSMEM>>>(qkvh, qkvl, ctx);
    // 4. x2 = x + ctx@wo + bo
    gemm_f16_pipe<1><<<gC, 256, GEMM_SMEM>>>(ctx, woT, bo, x,
                                             x2, nullptr, nullptr,
                                             NROWS, CC, CC);
    // 5. h = LN2(x2)  (fp16)
    ln_h_kernel<<<NROWS, 256>>>(x2, ln2w, ln2b, h);
    // 6. ff = gelu(h@w1 + b1)  (fp16 out)
    gemm_f16_pipe<2><<<gF, 256, GEMM_SMEM>>>(h, w1T, b1, nullptr,
                                             nullptr, ff, nullptr,
                                             NROWS, FFN, CC);
    // 7. out = x2 + ff@w2 + b2
    gemm_f16_pipe<1><<<gC, 256, GEMM_SMEM>>>(ff, w2T, b2, x2,
                                             out, nullptr, nullptr,
                                             NROWS, CC, FFN);
}